// round 1
// baseline (speedup 1.0000x reference)
#include <cuda_runtime.h>
#include <cuda_bf16.h>
#include <math.h>

// Problem constants
#define Tn 128
#define Bn 1024
#define In 128
#define Hn 256
#define Kn 8
#define E1n 512
#define E2n 256
#define Cn 2

// ---------------- device scratch (no allocations allowed) ----------------
__device__ float g_gi[(size_t)Tn * Bn * 3 * Hn];     // 402 MB, reused for layer0 and layer1 gi
__device__ float g_hseq[(size_t)Tn * Bn * Hn];       // layer-0 outputs
__device__ float g_hbuf0[Bn * Hn];
__device__ float g_hbuf1[Bn * Hn];
__device__ float g_q[Bn * Kn];
__device__ float g_Wt_ih0[In * 3 * Hn];
__device__ float g_Wt_hh0[Hn * 3 * Hn];
__device__ float g_Wt_ih1[Hn * 3 * Hn];
__device__ float g_Wt_hh1[Hn * 3 * Hn];
__device__ float g_Wt_e1[Kn * Hn * E1n];
__device__ float g_Wt_e2[Kn * E1n * E2n];
__device__ float g_h1[(size_t)Kn * Bn * E1n];
__device__ float g_h2[(size_t)Kn * Bn * E2n];

// ---------------- f32x2 packed math helpers (Blackwell FFMA2) ----------------
__device__ __forceinline__ unsigned long long pack2(float x, float y) {
    unsigned long long r;
    asm("mov.b64 %0, {%1, %2};" : "=l"(r) : "f"(x), "f"(y));
    return r;
}
__device__ __forceinline__ void ffma2(unsigned long long& d, unsigned long long a, unsigned long long b) {
    asm("fma.rn.f32x2 %0, %1, %2, %0;" : "+l"(d) : "l"(a), "l"(b));
}
__device__ __forceinline__ float2 unpack2(unsigned long long v) {
    float2 f;
    asm("mov.b64 {%0, %1}, %2;" : "=f"(f.x), "=f"(f.y) : "l"(v));
    return f;
}

// ---------------- generic batched transpose: in [batch,R,C] -> out [batch,C,R] ----------------
__global__ void transpose_k(const float* __restrict__ in, float* __restrict__ out, int R, int C)
{
    __shared__ float tile[32][33];
    const size_t boff = (size_t)blockIdx.z * R * C;
    int c0 = blockIdx.x * 32, r0 = blockIdx.y * 32;
    int tx = threadIdx.x, ty = threadIdx.y;
    #pragma unroll
    for (int i = ty; i < 32; i += 8) {
        int r = r0 + i, c = c0 + tx;
        if (r < R && c < C) tile[i][tx] = in[boff + (size_t)r * C + c];
    }
    __syncthreads();
    #pragma unroll
    for (int i = ty; i < 32; i += 8) {
        int c = c0 + i, r = r0 + tx;
        if (r < R && c < C) out[boff + (size_t)c * R + r] = tile[tx][i];
    }
}

// ---------------- 128x128x16 fp32x2 GEMM:  C = act(A @ Bt + bias) ----------------
// A row-major [M,K] (amode=1: row m maps to x[(m%B), (m/B), :] with lda=I)
// Bt row-major [K,N]; all dims multiples of tile sizes (guaranteed by caller).
__global__ __launch_bounds__(256) void gemm128(
    const float* __restrict__ A, const float* __restrict__ Bt,
    const float* __restrict__ bias, float* __restrict__ Cmat,
    int M, int N, int K, int lda, int amode, int relu,
    long long sA, long long sB, long long sBias, long long sC)
{
    const int bz = blockIdx.z;
    A    += (size_t)sA * bz;
    Bt   += (size_t)sB * bz;
    bias += (size_t)sBias * bz;
    Cmat += (size_t)sC * bz;
    const int n0 = blockIdx.x * 128;
    const int m0 = blockIdx.y * 128;

    __shared__ float As[16][132];   // [BK][BM+4] transposed A tile
    __shared__ float Bs[16][128];   // [BK][BN]

    const int tid = threadIdx.x;
    const int tx = tid & 15, ty = tid >> 4;
    const int arow0 = tid >> 2, aq = tid & 3;   // A loader: 2 rows (r, r+64), quad aq
    const int brow0 = tid >> 5, bq = tid & 31;  // B loader: rows (r, r+8), quad bq

    unsigned long long acc[8][4];
    #pragma unroll
    for (int i = 0; i < 8; i++)
        #pragma unroll
        for (int j = 0; j < 4; j++) acc[i][j] = 0ull;

    for (int k0 = 0; k0 < K; k0 += 16) {
        // load A tile (128 x 16), store transposed
        #pragma unroll
        for (int it = 0; it < 2; it++) {
            int r = arow0 + it * 64;
            int m = m0 + r;
            size_t base = (amode == 0)
                ? (size_t)m * lda
                : ((size_t)(m & (Bn - 1)) * Tn + (m >> 10)) * (size_t)lda;
            float4 v = *(const float4*)(A + base + k0 + aq * 4);
            As[aq * 4 + 0][r] = v.x; As[aq * 4 + 1][r] = v.y;
            As[aq * 4 + 2][r] = v.z; As[aq * 4 + 3][r] = v.w;
        }
        // load B tile (16 x 128)
        #pragma unroll
        for (int it = 0; it < 2; it++) {
            int r = brow0 + it * 8;
            float4 v = *(const float4*)(Bt + (size_t)(k0 + r) * N + n0 + bq * 4);
            *(float4*)&Bs[r][bq * 4] = v;
        }
        __syncthreads();
        #pragma unroll
        for (int k = 0; k < 16; k++) {
            float4 aA = *(const float4*)&As[k][ty * 4];
            float4 aB = *(const float4*)&As[k][64 + ty * 4];
            const ulonglong2 bA = *(const ulonglong2*)&Bs[k][tx * 4];
            const ulonglong2 bB = *(const ulonglong2*)&Bs[k][64 + tx * 4];
            unsigned long long b2[4] = { bA.x, bA.y, bB.x, bB.y };
            float a_[8] = { aA.x, aA.y, aA.z, aA.w, aB.x, aB.y, aB.z, aB.w };
            #pragma unroll
            for (int i = 0; i < 8; i++) {
                unsigned long long a2 = pack2(a_[i], a_[i]);
                #pragma unroll
                for (int j = 0; j < 4; j++) ffma2(acc[i][j], a2, b2[j]);
            }
        }
        __syncthreads();
    }

    // epilogue
    #pragma unroll
    for (int i = 0; i < 8; i++) {
        int r = (i < 4) ? (ty * 4 + i) : (64 + ty * 4 + (i - 4));
        size_t crow = (size_t)(m0 + r) * N;
        #pragma unroll
        for (int j = 0; j < 4; j++) {
            int c = n0 + ((j < 2) ? (tx * 4 + j * 2) : (64 + tx * 4 + (j - 2) * 2));
            float2 v = unpack2(acc[i][j]);
            v.x += bias[c]; v.y += bias[c + 1];
            if (relu) { v.x = fmaxf(v.x, 0.f); v.y = fmaxf(v.y, 0.f); }
            *(float2*)&Cmat[crow + c] = v;
        }
    }
}

// ---------------- fused GRU step: gh GEMM (all 3 gates) + gate math ----------------
// grid (Hn/32, Bn/64), 256 threads. Per-thread: 4 batch rows x 2 hidden cols x 3 gates.
__global__ __launch_bounds__(256) void gru_step(
    const float* __restrict__ hprev, float* __restrict__ hout,
    const float* __restrict__ gi,   // [T,B,3H]
    const float* __restrict__ Wt,   // [H, 3H]  (transposed W_hh)
    const float* __restrict__ bhh,  // [3H]
    float* __restrict__ hseq,       // [T,B,H] or nullptr
    int t, int first)
{
    const int n0 = blockIdx.x * 32;
    const int b0 = blockIdx.y * 64;
    __shared__ float Hs[16][68];
    __shared__ float Ws[16][96];
    const int tid = threadIdx.x;
    const int tx = tid & 15, ty = tid >> 4;

    unsigned long long accr[4], accz[4], accn[4];
    #pragma unroll
    for (int i = 0; i < 4; i++) { accr[i] = 0ull; accz[i] = 0ull; accn[i] = 0ull; }

    if (!first) {
        const int hrr = tid >> 2, hq = tid & 3;
        for (int k0 = 0; k0 < Hn; k0 += 16) {
            float4 hv = *(const float4*)(hprev + (size_t)(b0 + hrr) * Hn + k0 + hq * 4);
            Hs[hq * 4 + 0][hrr] = hv.x; Hs[hq * 4 + 1][hrr] = hv.y;
            Hs[hq * 4 + 2][hrr] = hv.z; Hs[hq * 4 + 3][hrr] = hv.w;
            #pragma unroll
            for (int it = 0; it < 6; it++) {
                int idx = tid + it * 256;           // 0..1535
                int k = idx / 96, c = idx - k * 96;
                int g = c >> 5, n = c & 31;
                Ws[k][c] = Wt[(size_t)(k0 + k) * (3 * Hn) + g * Hn + n0 + n];
            }
            __syncthreads();
            #pragma unroll
            for (int k = 0; k < 16; k++) {
                float4 a4 = *(const float4*)&Hs[k][ty * 4];
                unsigned long long br = *(const unsigned long long*)&Ws[k][tx * 2];
                unsigned long long bz = *(const unsigned long long*)&Ws[k][32 + tx * 2];
                unsigned long long bn = *(const unsigned long long*)&Ws[k][64 + tx * 2];
                float a_[4] = { a4.x, a4.y, a4.z, a4.w };
                #pragma unroll
                for (int i = 0; i < 4; i++) {
                    unsigned long long a2 = pack2(a_[i], a_[i]);
                    ffma2(accr[i], a2, br);
                    ffma2(accz[i], a2, bz);
                    ffma2(accn[i], a2, bn);
                }
            }
            __syncthreads();
        }
    }

    #pragma unroll
    for (int i = 0; i < 4; i++) {
        int b = b0 + ty * 4 + i;
        size_t gbase = ((size_t)t * Bn + b) * (3 * Hn);
        float2 r2 = unpack2(accr[i]);
        float2 z2 = unpack2(accz[i]);
        float2 n2 = unpack2(accn[i]);
        float rv[2] = { r2.x, r2.y }, zv[2] = { z2.x, z2.y }, nv[2] = { n2.x, n2.y };
        #pragma unroll
        for (int jj = 0; jj < 2; jj++) {
            int n = n0 + tx * 2 + jj;
            float grv = gi[gbase + n]            + rv[jj] + bhh[n];
            float gzv = gi[gbase + Hn + n]       + zv[jj] + bhh[Hn + n];
            float gin = gi[gbase + 2 * Hn + n];
            float ghn = nv[jj] + bhh[2 * Hn + n];
            float r = 1.f / (1.f + expf(-grv));
            float z = 1.f / (1.f + expf(-gzv));
            float nn = tanhf(gin + r * ghn);
            float hp = first ? 0.f : hprev[(size_t)b * Hn + n];
            float hv = (1.f - z) * nn + z * hp;
            hout[(size_t)b * Hn + n] = hv;
            if (hseq) hseq[((size_t)t * Bn + b) * Hn + n] = hv;
        }
    }
}

// ---------------- soft cluster assignment q (Student-t, alpha=1) ----------------
// one warp per batch row; grid 128 x 256 threads
__global__ __launch_bounds__(256) void qkernel(
    const float* __restrict__ z, const float* __restrict__ centers, float* __restrict__ q)
{
    __shared__ float cs[Kn * Hn];
    for (int i = threadIdx.x; i < Kn * Hn; i += 256) cs[i] = centers[i];
    __syncthreads();
    int warp = threadIdx.x >> 5, lane = threadIdx.x & 31;
    int b = blockIdx.x * 8 + warp;
    const float* zr = z + (size_t)b * Hn;
    float zv[8];
    #pragma unroll
    for (int i = 0; i < 8; i++) zv[i] = zr[lane + i * 32];
    float qk[Kn]; float s = 0.f;
    #pragma unroll
    for (int k = 0; k < Kn; k++) {
        float d2 = 0.f;
        #pragma unroll
        for (int i = 0; i < 8; i++) {
            float d = zv[i] - cs[k * Hn + lane + i * 32];
            d2 = fmaf(d, d, d2);
        }
        #pragma unroll
        for (int o = 16; o; o >>= 1) d2 += __shfl_xor_sync(0xffffffffu, d2, o);
        qk[k] = 1.f / (1.f + d2);
        s += qk[k];
    }
    if (lane == 0) {
        float inv = 1.f / s;
        #pragma unroll
        for (int k = 0; k < Kn; k++) q[b * Kn + k] = qk[k] * inv;
    }
}

// ---------------- final: logits + q-weighted combine ----------------
// one warp per batch row; grid 128 x 256 threads
__global__ __launch_bounds__(256) void expert_out(
    const float* __restrict__ h2,  // [K,B,E2]
    const float* __restrict__ W3,  // [K,C,E2]
    const float* __restrict__ b3,  // [K,C]
    const float* __restrict__ q,   // [B,K]
    float* __restrict__ out)       // [B,C]
{
    int warp = threadIdx.x >> 5, lane = threadIdx.x & 31;
    int b = blockIdx.x * 8 + warp;
    float p0 = 0.f, p1 = 0.f;
    #pragma unroll
    for (int k = 0; k < Kn; k++) {
        const float* hr = h2 + ((size_t)k * Bn + b) * E2n;
        const float* w0 = W3 + (size_t)(k * 2 + 0) * E2n;
        const float* w1 = W3 + (size_t)(k * 2 + 1) * E2n;
        float d0 = 0.f, d1 = 0.f;
        #pragma unroll
        for (int i = 0; i < 8; i++) {
            float hv = hr[lane + i * 32];
            d0 = fmaf(hv, w0[lane + i * 32], d0);
            d1 = fmaf(hv, w1[lane + i * 32], d1);
        }
        #pragma unroll
        for (int o = 16; o; o >>= 1) {
            d0 += __shfl_xor_sync(0xffffffffu, d0, o);
            d1 += __shfl_xor_sync(0xffffffffu, d1, o);
        }
        float qv = q[b * Kn + k];
        p0 += qv * (d0 + b3[k * 2 + 0]);
        p1 += qv * (d1 + b3[k * 2 + 1]);
    }
    if (lane == 0) { out[b * 2 + 0] = p0; out[b * 2 + 1] = p1; }
}

// ---------------- launch ----------------
extern "C" void kernel_launch(void* const* d_in, const int* in_sizes, int n_in,
                              void* d_out, int out_size)
{
    const float* x      = (const float*)d_in[0];
    const float* W_ih0  = (const float*)d_in[1];
    const float* W_hh0  = (const float*)d_in[2];
    const float* b_ih0  = (const float*)d_in[3];
    const float* b_hh0  = (const float*)d_in[4];
    const float* W_ih1  = (const float*)d_in[5];
    const float* W_hh1  = (const float*)d_in[6];
    const float* b_ih1  = (const float*)d_in[7];
    const float* b_hh1  = (const float*)d_in[8];
    const float* cc     = (const float*)d_in[9];
    const float* eW1    = (const float*)d_in[10];
    const float* eb1    = (const float*)d_in[11];
    const float* eW2    = (const float*)d_in[12];
    const float* eb2    = (const float*)d_in[13];
    const float* eW3    = (const float*)d_in[14];
    const float* eb3    = (const float*)d_in[15];
    float* out = (float*)d_out;

    float *gi, *hseq, *hb0, *hb1, *q, *wih0, *whh0, *wih1, *whh1, *we1, *we2, *h1, *h2;
    cudaGetSymbolAddress((void**)&gi,   g_gi);
    cudaGetSymbolAddress((void**)&hseq, g_hseq);
    cudaGetSymbolAddress((void**)&hb0,  g_hbuf0);
    cudaGetSymbolAddress((void**)&hb1,  g_hbuf1);
    cudaGetSymbolAddress((void**)&q,    g_q);
    cudaGetSymbolAddress((void**)&wih0, g_Wt_ih0);
    cudaGetSymbolAddress((void**)&whh0, g_Wt_hh0);
    cudaGetSymbolAddress((void**)&wih1, g_Wt_ih1);
    cudaGetSymbolAddress((void**)&whh1, g_Wt_hh1);
    cudaGetSymbolAddress((void**)&we1,  g_Wt_e1);
    cudaGetSymbolAddress((void**)&we2,  g_Wt_e2);
    cudaGetSymbolAddress((void**)&h1,   g_h1);
    cudaGetSymbolAddress((void**)&h2,   g_h2);

    dim3 tb(32, 8);
    // weight transposes: in [.,R,C] -> out [.,C,R], grid (C/32, R/32, batch)
    transpose_k<<<dim3(In  / 32, 3 * Hn / 32, 1),  tb>>>(W_ih0, wih0, 3 * Hn, In);
    transpose_k<<<dim3(Hn  / 32, 3 * Hn / 32, 1),  tb>>>(W_hh0, whh0, 3 * Hn, Hn);
    transpose_k<<<dim3(Hn  / 32, 3 * Hn / 32, 1),  tb>>>(W_ih1, wih1, 3 * Hn, Hn);
    transpose_k<<<dim3(Hn  / 32, 3 * Hn / 32, 1),  tb>>>(W_hh1, whh1, 3 * Hn, Hn);
    transpose_k<<<dim3(Hn  / 32, E1n / 32, Kn),    tb>>>(eW1, we1, E1n, Hn);
    transpose_k<<<dim3(E1n / 32, E2n / 32, Kn),    tb>>>(eW2, we2, E2n, E1n);

    const int M0 = Tn * Bn;  // 131072

    // gi0 = x @ W_ih0^T + b_ih0  (stored [T,B,3H])
    gemm128<<<dim3(3 * Hn / 128, M0 / 128, 1), 256>>>(
        x, wih0, b_ih0, gi, M0, 3 * Hn, In, In, /*amode=*/1, /*relu=*/0, 0, 0, 0, 0);

    // layer-0 recurrence (saves full sequence)
    for (int t = 0; t < Tn; t++) {
        const float* hp = (t & 1) ? hb1 : hb0;
        float*       ho = (t & 1) ? hb0 : hb1;
        gru_step<<<dim3(Hn / 32, Bn / 64), 256>>>(hp, ho, gi, whh0, b_hh0, hseq, t, t == 0);
    }

    // gi1 = h_l0 @ W_ih1^T + b_ih1  (reuse gi buffer)
    gemm128<<<dim3(3 * Hn / 128, M0 / 128, 1), 256>>>(
        hseq, wih1, b_ih1, gi, M0, 3 * Hn, Hn, Hn, 0, 0, 0, 0, 0, 0);

    // layer-1 recurrence (final hidden in hb0)
    for (int t = 0; t < Tn; t++) {
        const float* hp = (t & 1) ? hb1 : hb0;
        float*       ho = (t & 1) ? hb0 : hb1;
        gru_step<<<dim3(Hn / 32, Bn / 64), 256>>>(hp, ho, gi, whh1, b_hh1, nullptr, t, t == 0);
    }

    // q [B,K]
    qkernel<<<Bn / 8, 256>>>(hb0, cc, q);

    // experts (batched over K in grid.z)
    gemm128<<<dim3(E1n / 128, Bn / 128, Kn), 256>>>(
        hb0, we1, eb1, h1, Bn, E1n, Hn, Hn, 0, /*relu=*/1,
        0, (long long)Hn * E1n, E1n, (long long)Bn * E1n);
    gemm128<<<dim3(E2n / 128, Bn / 128, Kn), 256>>>(
        h1, we2, eb2, h2, Bn, E2n, E1n, E1n, 0, /*relu=*/1,
        (long long)Bn * E1n, (long long)E1n * E2n, E2n, (long long)Bn * E2n);

    // logits + q-weighted combine -> out [B,C]
    expert_out<<<Bn / 8, 256>>>(h2, eW3, eb3, q, out);
}

// round 2
// speedup vs baseline: 1.2685x; 1.2685x over previous
#include <cuda_runtime.h>
#include <math.h>

// Problem constants
#define Tn 128
#define Bn 1024
#define In 128
#define Hn 256
#define Kn 8
#define E1n 512
#define E2n 256

// ---------------- device scratch (no allocations allowed) ----------------
__device__ __align__(256) float g_gi[(size_t)Tn * Bn * 3 * Hn];
__device__ __align__(256) float g_hseq[(size_t)Tn * Bn * Hn];
__device__ __align__(256) float g_hbuf0[Bn * Hn];
__device__ __align__(256) float g_hbuf1[Bn * Hn];
__device__ __align__(256) float g_q[Bn * Kn];
__device__ __align__(256) float g_Wt_ih0[In * 3 * Hn];
__device__ __align__(256) float g_Wt_ih1[Hn * 3 * Hn];
__device__ __align__(256) float g_wp0[8 * Hn * 96];
__device__ __align__(256) float g_wp1[8 * Hn * 96];
__device__ __align__(256) float g_bsum0[3 * Hn];
__device__ __align__(256) float g_bsum1[3 * Hn];
__device__ __align__(256) float g_Wt_e1[Kn * Hn * E1n];
__device__ __align__(256) float g_Wt_e2[Kn * E1n * E2n];
__device__ __align__(256) float g_h1[(size_t)Kn * Bn * E1n];
__device__ __align__(256) float g_h2[(size_t)Kn * Bn * E2n];

// ---------------- f32x2 packed math helpers (Blackwell FFMA2) ----------------
__device__ __forceinline__ unsigned long long pack2(float x, float y) {
    unsigned long long r;
    asm("mov.b64 %0, {%1, %2};" : "=l"(r) : "f"(x), "f"(y));
    return r;
}
__device__ __forceinline__ void ffma2(unsigned long long& d, unsigned long long a, unsigned long long b) {
    asm("fma.rn.f32x2 %0, %1, %2, %0;" : "+l"(d) : "l"(a), "l"(b));
}
__device__ __forceinline__ float2 unpack2(unsigned long long v) {
    float2 f;
    asm("mov.b64 {%0, %1}, %2;" : "=f"(f.x), "=f"(f.y) : "l"(v));
    return f;
}

// ---------------- fused transpose (all weight transposes in ONE launch) ----------------
struct TJob { const float* in; float* out; int R, C, tC, tpb, off; };
struct TJobs { TJob j[4]; };

__global__ void transpose_all(TJobs js)
{
    __shared__ float tile[32][33];
    int bx = blockIdx.x;
    int ji = 0;
    if (bx >= js.j[1].off) ji = 1;
    if (bx >= js.j[2].off) ji = 2;
    if (bx >= js.j[3].off) ji = 3;
    TJob jb = js.j[ji];
    int local = bx - jb.off;
    int batch = local / jb.tpb;
    int rem = local - batch * jb.tpb;
    int cIdx = rem % jb.tC, rIdx = rem / jb.tC;
    size_t boff = (size_t)batch * jb.R * jb.C;
    int c0 = cIdx * 32, r0 = rIdx * 32;
    int tx = threadIdx.x, ty = threadIdx.y;
    #pragma unroll
    for (int i = ty; i < 32; i += 8)
        tile[i][tx] = jb.in[boff + (size_t)(r0 + i) * jb.C + c0 + tx];
    __syncthreads();
    #pragma unroll
    for (int i = ty; i < 32; i += 8)
        jb.out[boff + (size_t)(c0 + i) * jb.R + r0 + tx] = tile[tx][i];
}

// ---------------- pack W_hh into per-nblk contiguous [nblk][k][96] ----------------
__global__ void pack_whh(const float* __restrict__ W0, const float* __restrict__ W1,
                         float* __restrict__ P0, float* __restrict__ P1)
{
    const float* W = blockIdx.z ? W1 : W0;
    float* P = blockIdx.z ? P1 : P0;
    int nblk = blockIdx.x, k0 = blockIdx.y * 32;
    __shared__ float tile[96][33];
    int tx = threadIdx.x & 31, ty = threadIdx.x >> 5;  // 32 x 8
    for (int j = ty; j < 96; j += 8) {
        int row = (j >> 5) * Hn + nblk * 32 + (j & 31);
        tile[j][tx] = W[(size_t)row * Hn + k0 + tx];
    }
    __syncthreads();
    for (int idx = threadIdx.x; idx < 32 * 96; idx += 256) {
        int kk = idx / 96, c = idx - kk * 96;
        P[((size_t)nblk * Hn + k0 + kk) * 96 + c] = tile[c][kk];
    }
}

// ---------------- bias combine: fold b_hh (r,z gates) into gi bias ----------------
__global__ void bias_combine(const float* bih0, const float* bhh0,
                             const float* bih1, const float* bhh1,
                             float* o0, float* o1)
{
    int i = threadIdx.x;  // 768
    o0[i] = bih0[i] + (i < 2 * Hn ? bhh0[i] : 0.f);
    o1[i] = bih1[i] + (i < 2 * Hn ? bhh1[i] : 0.f);
}

// ---------------- double-buffered 128x128x16 fp32x2 GEMM: C = act(A @ Bt + bias) ----------------
__global__ __launch_bounds__(256, 2) void gemm128(
    const float* __restrict__ A, const float* __restrict__ Bt,
    const float* __restrict__ bias, float* __restrict__ Cmat,
    int M, int N, int K, int lda, int amode, int relu,
    long long sA, long long sB, long long sBias, long long sC)
{
    const int bz = blockIdx.z;
    A    += (size_t)sA * bz;
    Bt   += (size_t)sB * bz;
    bias += (size_t)sBias * bz;
    Cmat += (size_t)sC * bz;
    const int n0 = blockIdx.x * 128;
    const int m0 = blockIdx.y * 128;

    __shared__ float As[2][16][132];
    __shared__ float Bs[2][16][128];

    const int tid = threadIdx.x;
    const int tx = tid & 15, ty = tid >> 4;
    const int arow0 = tid >> 2, aq = tid & 3;
    const int brow0 = tid >> 5, bq = tid & 31;

    size_t ab0, ab1;
    { int m = m0 + arow0;
      ab0 = (amode == 0) ? (size_t)m * lda
                         : ((size_t)(m & (Bn - 1)) * Tn + (m >> 10)) * (size_t)lda; }
    { int m = m0 + arow0 + 64;
      ab1 = (amode == 0) ? (size_t)m * lda
                         : ((size_t)(m & (Bn - 1)) * Tn + (m >> 10)) * (size_t)lda; }
    const float* Ap0 = A + ab0 + aq * 4;
    const float* Ap1 = A + ab1 + aq * 4;
    const float* Bp0 = Bt + (size_t)brow0 * N + n0 + bq * 4;
    const float* Bp1 = Bt + (size_t)(brow0 + 8) * N + n0 + bq * 4;

    unsigned long long acc[8][4];
    #pragma unroll
    for (int i = 0; i < 8; i++)
        #pragma unroll
        for (int j = 0; j < 4; j++) acc[i][j] = 0ull;

    // prologue: tile 0 -> buf 0
    float4 pa0 = *(const float4*)(Ap0);
    float4 pa1 = *(const float4*)(Ap1);
    float4 pb0 = *(const float4*)(Bp0);
    float4 pb1 = *(const float4*)(Bp1);
    As[0][aq * 4 + 0][arow0] = pa0.x; As[0][aq * 4 + 1][arow0] = pa0.y;
    As[0][aq * 4 + 2][arow0] = pa0.z; As[0][aq * 4 + 3][arow0] = pa0.w;
    As[0][aq * 4 + 0][arow0 + 64] = pa1.x; As[0][aq * 4 + 1][arow0 + 64] = pa1.y;
    As[0][aq * 4 + 2][arow0 + 64] = pa1.z; As[0][aq * 4 + 3][arow0 + 64] = pa1.w;
    *(float4*)&Bs[0][brow0][bq * 4] = pb0;
    *(float4*)&Bs[0][brow0 + 8][bq * 4] = pb1;
    __syncthreads();

    const int nit = K >> 4;
    for (int it = 0; it < nit; ++it) {
        const int cur = it & 1;
        const bool more = (it + 1) < nit;
        if (more) {
            const int k0 = (it + 1) << 4;
            pa0 = *(const float4*)(Ap0 + k0);
            pa1 = *(const float4*)(Ap1 + k0);
            pb0 = *(const float4*)(Bp0 + (size_t)k0 * N);
            pb1 = *(const float4*)(Bp1 + (size_t)k0 * N);
        }
        #pragma unroll
        for (int k = 0; k < 16; k++) {
            float4 aA = *(const float4*)&As[cur][k][ty * 4];
            float4 aB = *(const float4*)&As[cur][k][64 + ty * 4];
            ulonglong2 bA = *(const ulonglong2*)&Bs[cur][k][tx * 4];
            ulonglong2 bB = *(const ulonglong2*)&Bs[cur][k][64 + tx * 4];
            unsigned long long b2[4] = { bA.x, bA.y, bB.x, bB.y };
            float a_[8] = { aA.x, aA.y, aA.z, aA.w, aB.x, aB.y, aB.z, aB.w };
            #pragma unroll
            for (int i = 0; i < 8; i++) {
                unsigned long long a2 = pack2(a_[i], a_[i]);
                #pragma unroll
                for (int j = 0; j < 4; j++) ffma2(acc[i][j], a2, b2[j]);
            }
        }
        if (more) {
            const int nb = cur ^ 1;
            As[nb][aq * 4 + 0][arow0] = pa0.x; As[nb][aq * 4 + 1][arow0] = pa0.y;
            As[nb][aq * 4 + 2][arow0] = pa0.z; As[nb][aq * 4 + 3][arow0] = pa0.w;
            As[nb][aq * 4 + 0][arow0 + 64] = pa1.x; As[nb][aq * 4 + 1][arow0 + 64] = pa1.y;
            As[nb][aq * 4 + 2][arow0 + 64] = pa1.z; As[nb][aq * 4 + 3][arow0 + 64] = pa1.w;
            *(float4*)&Bs[nb][brow0][bq * 4] = pb0;
            *(float4*)&Bs[nb][brow0 + 8][bq * 4] = pb1;
            __syncthreads();
        }
    }

    // epilogue
    #pragma unroll
    for (int i = 0; i < 8; i++) {
        int r = (i < 4) ? (ty * 4 + i) : (64 + ty * 4 + (i - 4));
        size_t crow = (size_t)(m0 + r) * N;
        #pragma unroll
        for (int j = 0; j < 4; j++) {
            int c = n0 + ((j < 2) ? (tx * 4 + j * 2) : (64 + tx * 4 + (j - 2) * 2));
            float2 v = unpack2(acc[i][j]);
            v.x += bias[c]; v.y += bias[c + 1];
            if (relu) { v.x = fmaxf(v.x, 0.f); v.y = fmaxf(v.y, 0.f); }
            *(float2*)&Cmat[crow + c] = v;
        }
    }
}

// ---------------- fused GRU step: gh GEMM (all 3 gates) + gate math ----------------
// grid (8, Bn/64), 256 threads, double-buffered smem, packed contiguous W.
__global__ __launch_bounds__(256, 2) void gru_step(
    const float* __restrict__ hprev, float* __restrict__ hout,
    const float* __restrict__ gi,    // [T,B,3H] (bias bsum folded in)
    const float* __restrict__ wpack, // [8][Hn][96]
    const float* __restrict__ bhh,   // original b_hh (only n-gate slice used)
    int t, int first)
{
    const int nblk = blockIdx.x;
    const int b0 = blockIdx.y * 64;
    const int n0 = nblk * 32;
    __shared__ float Hs[2][16][68];
    __shared__ float Ws[2][16][96];
    const int tid = threadIdx.x;
    const int tx = tid & 15, ty = tid >> 4;
    const float* Wt = wpack + (size_t)nblk * Hn * 96;

    unsigned long long accr[4], accz[4], accn[4];
    #pragma unroll
    for (int i = 0; i < 4; i++) { accr[i] = 0ull; accz[i] = 0ull; accn[i] = 0ull; }

    if (!first) {
        const int hr = tid >> 2, hq = tid & 3;
        const float* Hp = hprev + (size_t)(b0 + hr) * Hn + hq * 4;
        const bool w1ok = tid < 128;
        const int k1 = tid / 24,          c1 = tid - 24 * (tid / 24);
        const int i2 = tid + 256;
        const int k2 = i2 / 24,           c2 = i2 - 24 * (i2 / 24);

        float4 ph  = *(const float4*)(Hp);
        float4 pw0 = *(const float4*)(Wt + tid * 4);
        float4 pw1 = make_float4(0.f, 0.f, 0.f, 0.f);
        if (w1ok) pw1 = *(const float4*)(Wt + (size_t)i2 * 4);
        Hs[0][hq * 4 + 0][hr] = ph.x; Hs[0][hq * 4 + 1][hr] = ph.y;
        Hs[0][hq * 4 + 2][hr] = ph.z; Hs[0][hq * 4 + 3][hr] = ph.w;
        *(float4*)&Ws[0][k1][c1 * 4] = pw0;
        if (w1ok) *(float4*)&Ws[0][k2][c2 * 4] = pw1;
        __syncthreads();

        for (int it = 0; it < 16; ++it) {
            const int cur = it & 1;
            const bool more = it < 15;
            if (more) {
                const int k0 = (it + 1) * 16;
                ph  = *(const float4*)(Hp + k0);
                pw0 = *(const float4*)(Wt + (size_t)k0 * 96 + tid * 4);
                if (w1ok) pw1 = *(const float4*)(Wt + (size_t)k0 * 96 + (size_t)i2 * 4);
            }
            #pragma unroll
            for (int k = 0; k < 16; k++) {
                float4 a4 = *(const float4*)&Hs[cur][k][ty * 4];
                const float* wk = &Ws[cur][k][0];
                unsigned long long br = *(const unsigned long long*)(wk + tx * 2);
                unsigned long long bz = *(const unsigned long long*)(wk + 32 + tx * 2);
                unsigned long long bn = *(const unsigned long long*)(wk + 64 + tx * 2);
                float a_[4] = { a4.x, a4.y, a4.z, a4.w };
                #pragma unroll
                for (int i = 0; i < 4; i++) {
                    unsigned long long a2 = pack2(a_[i], a_[i]);
                    ffma2(accr[i], a2, br);
                    ffma2(accz[i], a2, bz);
                    ffma2(accn[i], a2, bn);
                }
            }
            if (more) {
                const int nb = cur ^ 1;
                Hs[nb][hq * 4 + 0][hr] = ph.x; Hs[nb][hq * 4 + 1][hr] = ph.y;
                Hs[nb][hq * 4 + 2][hr] = ph.z; Hs[nb][hq * 4 + 3][hr] = ph.w;
                *(float4*)&Ws[nb][k1][c1 * 4] = pw0;
                if (w1ok) *(float4*)&Ws[nb][k2][c2 * 4] = pw1;
                __syncthreads();
            }
        }
    }

    // gate math epilogue (fast intrinsics; error ~1e-7, tolerance 1e-3)
    #pragma unroll
    for (int i = 0; i < 4; i++) {
        int b = b0 + ty * 4 + i;
        size_t gb = ((size_t)t * Bn + b) * (3 * Hn);
        int n = n0 + tx * 2;
        float2 r2 = unpack2(accr[i]), z2 = unpack2(accz[i]), n2 = unpack2(accn[i]);
        float2 gr = *(const float2*)&gi[gb + n];
        float2 gz = *(const float2*)&gi[gb + Hn + n];
        float2 gn = *(const float2*)&gi[gb + 2 * Hn + n];
        float2 bn2 = *(const float2*)&bhh[2 * Hn + n];
        float2 hp2 = make_float2(0.f, 0.f);
        if (!first) hp2 = *(const float2*)&hprev[(size_t)b * Hn + n];
        float rr[2] = { r2.x, r2.y }, zz[2] = { z2.x, z2.y }, nv[2] = { n2.x, n2.y };
        float grv[2] = { gr.x, gr.y }, gzv[2] = { gz.x, gz.y }, gnv[2] = { gn.x, gn.y };
        float bnn[2] = { bn2.x, bn2.y }, hpv[2] = { hp2.x, hp2.y };
        float outv[2];
        #pragma unroll
        for (int jj = 0; jj < 2; jj++) {
            float r = __fdividef(1.f, 1.f + __expf(-(grv[jj] + rr[jj])));
            float z = __fdividef(1.f, 1.f + __expf(-(gzv[jj] + zz[jj])));
            float a = gnv[jj] + r * (nv[jj] + bnn[jj]);
            float e = __expf(2.f * a);
            float nn = 1.f - __fdividef(2.f, e + 1.f);
            outv[jj] = (1.f - z) * nn + z * hpv[jj];
        }
        *(float2*)&hout[(size_t)b * Hn + n] = make_float2(outv[0], outv[1]);
    }
}

// ---------------- soft cluster assignment q (Student-t, alpha=1) ----------------
__global__ __launch_bounds__(256) void qkernel(
    const float* __restrict__ z, const float* __restrict__ centers, float* __restrict__ q)
{
    __shared__ float cs[Kn * Hn];
    for (int i = threadIdx.x; i < Kn * Hn; i += 256) cs[i] = centers[i];
    __syncthreads();
    int warp = threadIdx.x >> 5, lane = threadIdx.x & 31;
    int b = blockIdx.x * 8 + warp;
    const float* zr = z + (size_t)b * Hn;
    float zv[8];
    #pragma unroll
    for (int i = 0; i < 8; i++) zv[i] = zr[lane + i * 32];
    float qk[Kn]; float s = 0.f;
    #pragma unroll
    for (int k = 0; k < Kn; k++) {
        float d2 = 0.f;
        #pragma unroll
        for (int i = 0; i < 8; i++) {
            float d = zv[i] - cs[k * Hn + lane + i * 32];
            d2 = fmaf(d, d, d2);
        }
        #pragma unroll
        for (int o = 16; o; o >>= 1) d2 += __shfl_xor_sync(0xffffffffu, d2, o);
        qk[k] = 1.f / (1.f + d2);
        s += qk[k];
    }
    if (lane == 0) {
        float inv = 1.f / s;
        #pragma unroll
        for (int k = 0; k < Kn; k++) q[b * Kn + k] = qk[k] * inv;
    }
}

// ---------------- final: logits + q-weighted combine ----------------
__global__ __launch_bounds__(256) void expert_out(
    const float* __restrict__ h2,  // [K,B,E2]
    const float* __restrict__ W3,  // [K,C,E2]
    const float* __restrict__ b3,  // [K,C]
    const float* __restrict__ q,   // [B,K]
    float* __restrict__ out)       // [B,C]
{
    int warp = threadIdx.x >> 5, lane = threadIdx.x & 31;
    int b = blockIdx.x * 8 + warp;
    float p0 = 0.f, p1 = 0.f;
    #pragma unroll
    for (int k = 0; k < Kn; k++) {
        const float* hr = h2 + ((size_t)k * Bn + b) * E2n;
        const float* w0 = W3 + (size_t)(k * 2 + 0) * E2n;
        const float* w1 = W3 + (size_t)(k * 2 + 1) * E2n;
        float d0 = 0.f, d1 = 0.f;
        #pragma unroll
        for (int i = 0; i < 8; i++) {
            float hv = hr[lane + i * 32];
            d0 = fmaf(hv, w0[lane + i * 32], d0);
            d1 = fmaf(hv, w1[lane + i * 32], d1);
        }
        #pragma unroll
        for (int o = 16; o; o >>= 1) {
            d0 += __shfl_xor_sync(0xffffffffu, d0, o);
            d1 += __shfl_xor_sync(0xffffffffu, d1, o);
        }
        float qv = q[b * Kn + k];
        p0 += qv * (d0 + b3[k * 2 + 0]);
        p1 += qv * (d1 + b3[k * 2 + 1]);
    }
    if (lane == 0) { out[b * 2 + 0] = p0; out[b * 2 + 1] = p1; }
}

// ---------------- launch ----------------
extern "C" void kernel_launch(void* const* d_in, const int* in_sizes, int n_in,
                              void* d_out, int out_size)
{
    const float* x      = (const float*)d_in[0];
    const float* W_ih0  = (const float*)d_in[1];
    const float* W_hh0  = (const float*)d_in[2];
    const float* b_ih0  = (const float*)d_in[3];
    const float* b_hh0  = (const float*)d_in[4];
    const float* W_ih1  = (const float*)d_in[5];
    const float* W_hh1  = (const float*)d_in[6];
    const float* b_ih1  = (const float*)d_in[7];
    const float* b_hh1  = (const float*)d_in[8];
    const float* cc     = (const float*)d_in[9];
    const float* eW1    = (const float*)d_in[10];
    const float* eb1    = (const float*)d_in[11];
    const float* eW2    = (const float*)d_in[12];
    const float* eb2    = (const float*)d_in[13];
    const float* eW3    = (const float*)d_in[14];
    const float* eb3    = (const float*)d_in[15];
    float* out = (float*)d_out;

    float *gi, *hseq, *hb0, *hb1, *q, *wih0, *wih1, *wp0, *wp1, *bs0, *bs1, *we1, *we2, *h1, *h2;
    cudaGetSymbolAddress((void**)&gi,   g_gi);
    cudaGetSymbolAddress((void**)&hseq, g_hseq);
    cudaGetSymbolAddress((void**)&hb0,  g_hbuf0);
    cudaGetSymbolAddress((void**)&hb1,  g_hbuf1);
    cudaGetSymbolAddress((void**)&q,    g_q);
    cudaGetSymbolAddress((void**)&wih0, g_Wt_ih0);
    cudaGetSymbolAddress((void**)&wih1, g_Wt_ih1);
    cudaGetSymbolAddress((void**)&wp0,  g_wp0);
    cudaGetSymbolAddress((void**)&wp1,  g_wp1);
    cudaGetSymbolAddress((void**)&bs0,  g_bsum0);
    cudaGetSymbolAddress((void**)&bs1,  g_bsum1);
    cudaGetSymbolAddress((void**)&we1,  g_Wt_e1);
    cudaGetSymbolAddress((void**)&we2,  g_Wt_e2);
    cudaGetSymbolAddress((void**)&h1,   g_h1);
    cudaGetSymbolAddress((void**)&h2,   g_h2);

    // ---- launch 1: all transposes fused ----
    TJobs js;
    js.j[0] = { W_ih0, wih0, 3 * Hn, In,  In  / 32, (3 * Hn / 32) * (In  / 32), 0 };
    js.j[1] = { W_ih1, wih1, 3 * Hn, Hn,  Hn  / 32, (3 * Hn / 32) * (Hn  / 32), 0 };
    js.j[2] = { eW1,   we1,  E1n,    Hn,  Hn  / 32, (E1n / 32) * (Hn  / 32), 0 };
    js.j[3] = { eW2,   we2,  E2n,    E1n, E1n / 32, (E2n / 32) * (E1n / 32), 0 };
    js.j[1].off = js.j[0].off + js.j[0].tpb;           // 96
    js.j[2].off = js.j[1].off + js.j[1].tpb;           // 288
    js.j[3].off = js.j[2].off + js.j[2].tpb * Kn;      // 1312
    int totalTiles = js.j[3].off + js.j[3].tpb * Kn;   // 2336
    transpose_all<<<totalTiles, dim3(32, 8)>>>(js);

    // ---- launch 2: pack W_hh for both layers ----
    pack_whh<<<dim3(8, 8, 2), 256>>>(W_hh0, W_hh1, wp0, wp1);

    // ---- launch 3: fold b_hh(r,z) into gi bias ----
    bias_combine<<<1, 3 * Hn>>>(b_ih0, b_hh0, b_ih1, b_hh1, bs0, bs1);

    const int M0 = Tn * Bn;  // 131072

    // ---- launch 4: gi0 = x @ W_ih0^T + bsum0, stored [T,B,3H] ----
    gemm128<<<dim3(3 * Hn / 128, M0 / 128, 1), 256>>>(
        x, wih0, bs0, gi, M0, 3 * Hn, In, In, /*amode=*/1, /*relu=*/0, 0, 0, 0, 0);

    // ---- layer-0 recurrence: sequence lives in hseq directly ----
    for (int t = 0; t < Tn; t++) {
        const float* hp = (t == 0) ? hseq : hseq + (size_t)(t - 1) * Bn * Hn;
        float*       ho = hseq + (size_t)t * Bn * Hn;
        gru_step<<<dim3(8, Bn / 64), 256>>>(hp, ho, gi, wp0, b_hh0, t, t == 0);
    }

    // ---- gi1 = h_l0 @ W_ih1^T + bsum1 (reuse gi buffer) ----
    gemm128<<<dim3(3 * Hn / 128, M0 / 128, 1), 256>>>(
        hseq, wih1, bs1, gi, M0, 3 * Hn, Hn, Hn, 0, 0, 0, 0, 0, 0);

    // ---- layer-1 recurrence (final hidden ends in hb0) ----
    for (int t = 0; t < Tn; t++) {
        const float* hp = (t & 1) ? hb1 : hb0;
        float*       ho = (t & 1) ? hb0 : hb1;
        gru_step<<<dim3(8, Bn / 64), 256>>>(hp, ho, gi, wp1, b_hh1, t, t == 0);
    }

    // ---- q [B,K] ----
    qkernel<<<Bn / 8, 256>>>(hb0, cc, q);

    // ---- experts (batched over K in grid.z) ----
    gemm128<<<dim3(E1n / 128, Bn / 128, Kn), 256>>>(
        hb0, we1, eb1, h1, Bn, E1n, Hn, Hn, 0, /*relu=*/1,
        0, (long long)Hn * E1n, E1n, (long long)Bn * E1n);
    gemm128<<<dim3(E2n / 128, Bn / 128, Kn), 256>>>(
        h1, we2, eb2, h2, Bn, E2n, E1n, E1n, 0, /*relu=*/1,
        (long long)Bn * E1n, (long long)E1n * E2n, E2n, (long long)Bn * E2n);

    // ---- logits + q-weighted combine -> out [B,C] ----
    expert_out<<<Bn / 8, 256>>>(h2, eW3, eb3, q, out);
}

// round 3
// speedup vs baseline: 1.4507x; 1.1437x over previous
#include <cuda_runtime.h>
#include <math.h>

// Problem constants
#define Tn 128
#define Bn 1024
#define In 128
#define Hn 256
#define Kn 8
#define E1n 512
#define E2n 256
#define NCTA 128

// ---------------- device scratch (no allocations allowed) ----------------
__device__ __align__(256) float g_gi[(size_t)Tn * Bn * 3 * Hn];
__device__ __align__(256) float g_hseq[(size_t)Tn * Bn * Hn];
__device__ __align__(256) float g_hbuf0[Bn * Hn];
__device__ __align__(256) float g_hbuf1[Bn * Hn];
__device__ __align__(256) float g_q[Bn * Kn];
__device__ __align__(256) float g_Wt_ih0[In * 3 * Hn];
__device__ __align__(256) float g_Wt_ih1[Hn * 3 * Hn];
__device__ __align__(256) float g_wp0[8 * Hn * 96];
__device__ __align__(256) float g_wp1[8 * Hn * 96];
__device__ __align__(256) float g_bsum0[3 * Hn];
__device__ __align__(256) float g_bsum1[3 * Hn];
__device__ __align__(256) float g_Wt_e1[Kn * Hn * E1n];
__device__ __align__(256) float g_Wt_e2[Kn * E1n * E2n];
__device__ __align__(256) float g_h1[(size_t)Kn * Bn * E1n];
__device__ __align__(256) float g_h2[(size_t)Kn * Bn * E2n];

// grid-barrier state (zero-initialized at module load; count self-resets)
__device__ unsigned g_bar_cnt;
__device__ unsigned g_bar_ph;

// ---------------- f32x2 packed math helpers (Blackwell FFMA2) ----------------
__device__ __forceinline__ unsigned long long pack2(float x, float y) {
    unsigned long long r;
    asm("mov.b64 %0, {%1, %2};" : "=l"(r) : "f"(x), "f"(y));
    return r;
}
__device__ __forceinline__ void ffma2(unsigned long long& d, unsigned long long a, unsigned long long b) {
    asm("fma.rn.f32x2 %0, %1, %2, %0;" : "+l"(d) : "l"(a), "l"(b));
}
__device__ __forceinline__ float2 unpack2(unsigned long long v) {
    float2 f;
    asm("mov.b64 {%0, %1}, %2;" : "=f"(f.x), "=f"(f.y) : "l"(v));
    return f;
}

__device__ __forceinline__ void grid_barrier() {
    __syncthreads();
    if (threadIdx.x == 0) {
        volatile unsigned* vph = &g_bar_ph;
        unsigned ph = *vph;
        __threadfence();
        unsigned old = atomicAdd(&g_bar_cnt, 1u);
        if (old == (unsigned)(NCTA - 1)) {
            atomicExch(&g_bar_cnt, 0u);
            __threadfence();
            atomicAdd(&g_bar_ph, 1u);
        } else {
            while (*vph == ph) { __nanosleep(32); }
        }
    }
    __syncthreads();
}

// ---------------- fused transpose (all weight transposes in ONE launch) ----------------
struct TJob { const float* in; float* out; int R, C, tC, tpb, off; };
struct TJobs { TJob j[4]; };

__global__ void transpose_all(TJobs js)
{
    __shared__ float tile[32][33];
    int bx = blockIdx.x;
    int ji = 0;
    if (bx >= js.j[1].off) ji = 1;
    if (bx >= js.j[2].off) ji = 2;
    if (bx >= js.j[3].off) ji = 3;
    TJob jb = js.j[ji];
    int local = bx - jb.off;
    int batch = local / jb.tpb;
    int rem = local - batch * jb.tpb;
    int cIdx = rem % jb.tC, rIdx = rem / jb.tC;
    size_t boff = (size_t)batch * jb.R * jb.C;
    int c0 = cIdx * 32, r0 = rIdx * 32;
    int tx = threadIdx.x, ty = threadIdx.y;
    #pragma unroll
    for (int i = ty; i < 32; i += 8)
        tile[i][tx] = jb.in[boff + (size_t)(r0 + i) * jb.C + c0 + tx];
    __syncthreads();
    #pragma unroll
    for (int i = ty; i < 32; i += 8)
        jb.out[boff + (size_t)(c0 + i) * jb.R + r0 + tx] = tile[tx][i];
}

// ---------------- pack W_hh into per-nblk contiguous [nblk][k][96] ----------------
__global__ void pack_whh(const float* __restrict__ W0, const float* __restrict__ W1,
                         float* __restrict__ P0, float* __restrict__ P1)
{
    const float* W = blockIdx.z ? W1 : W0;
    float* P = blockIdx.z ? P1 : P0;
    int nblk = blockIdx.x, k0 = blockIdx.y * 32;
    __shared__ float tile[96][33];
    int tx = threadIdx.x & 31, ty = threadIdx.x >> 5;  // 32 x 8
    for (int j = ty; j < 96; j += 8) {
        int row = (j >> 5) * Hn + nblk * 32 + (j & 31);
        tile[j][tx] = W[(size_t)row * Hn + k0 + tx];
    }
    __syncthreads();
    for (int idx = threadIdx.x; idx < 32 * 96; idx += 256) {
        int kk = idx / 96, c = idx - kk * 96;
        P[((size_t)nblk * Hn + k0 + kk) * 96 + c] = tile[c][kk];
    }
}

// ---------------- bias combine: fold b_hh (r,z gates) into gi bias ----------------
__global__ void bias_combine(const float* bih0, const float* bhh0,
                             const float* bih1, const float* bhh1,
                             float* o0, float* o1)
{
    int i = threadIdx.x;  // 768
    o0[i] = bih0[i] + (i < 2 * Hn ? bhh0[i] : 0.f);
    o1[i] = bih1[i] + (i < 2 * Hn ? bhh1[i] : 0.f);
}

// ---------------- double-buffered 128x128x16 fp32x2 GEMM: C = act(A @ Bt + bias) ----------------
__global__ __launch_bounds__(256, 2) void gemm128(
    const float* __restrict__ A, const float* __restrict__ Bt,
    const float* __restrict__ bias, float* __restrict__ Cmat,
    int M, int N, int K, int lda, int amode, int relu,
    long long sA, long long sB, long long sBias, long long sC)
{
    const int bz = blockIdx.z;
    A    += (size_t)sA * bz;
    Bt   += (size_t)sB * bz;
    bias += (size_t)sBias * bz;
    Cmat += (size_t)sC * bz;
    const int n0 = blockIdx.x * 128;
    const int m0 = blockIdx.y * 128;

    __shared__ float As[2][16][132];
    __shared__ float Bs[2][16][128];

    const int tid = threadIdx.x;
    const int tx = tid & 15, ty = tid >> 4;
    const int arow0 = tid >> 2, aq = tid & 3;
    const int brow0 = tid >> 5, bq = tid & 31;

    size_t ab0, ab1;
    { int m = m0 + arow0;
      ab0 = (amode == 0) ? (size_t)m * lda
                         : ((size_t)(m & (Bn - 1)) * Tn + (m >> 10)) * (size_t)lda; }
    { int m = m0 + arow0 + 64;
      ab1 = (amode == 0) ? (size_t)m * lda
                         : ((size_t)(m & (Bn - 1)) * Tn + (m >> 10)) * (size_t)lda; }
    const float* Ap0 = A + ab0 + aq * 4;
    const float* Ap1 = A + ab1 + aq * 4;
    const float* Bp0 = Bt + (size_t)brow0 * N + n0 + bq * 4;
    const float* Bp1 = Bt + (size_t)(brow0 + 8) * N + n0 + bq * 4;

    unsigned long long acc[8][4];
    #pragma unroll
    for (int i = 0; i < 8; i++)
        #pragma unroll
        for (int j = 0; j < 4; j++) acc[i][j] = 0ull;

    // prologue: tile 0 -> buf 0
    float4 pa0 = *(const float4*)(Ap0);
    float4 pa1 = *(const float4*)(Ap1);
    float4 pb0 = *(const float4*)(Bp0);
    float4 pb1 = *(const float4*)(Bp1);
    As[0][aq * 4 + 0][arow0] = pa0.x; As[0][aq * 4 + 1][arow0] = pa0.y;
    As[0][aq * 4 + 2][arow0] = pa0.z; As[0][aq * 4 + 3][arow0] = pa0.w;
    As[0][aq * 4 + 0][arow0 + 64] = pa1.x; As[0][aq * 4 + 1][arow0 + 64] = pa1.y;
    As[0][aq * 4 + 2][arow0 + 64] = pa1.z; As[0][aq * 4 + 3][arow0 + 64] = pa1.w;
    *(float4*)&Bs[0][brow0][bq * 4] = pb0;
    *(float4*)&Bs[0][brow0 + 8][bq * 4] = pb1;
    __syncthreads();

    const int nit = K >> 4;
    for (int it = 0; it < nit; ++it) {
        const int cur = it & 1;
        const bool more = (it + 1) < nit;
        if (more) {
            const int k0 = (it + 1) << 4;
            pa0 = *(const float4*)(Ap0 + k0);
            pa1 = *(const float4*)(Ap1 + k0);
            pb0 = *(const float4*)(Bp0 + (size_t)k0 * N);
            pb1 = *(const float4*)(Bp1 + (size_t)k0 * N);
        }
        #pragma unroll
        for (int k = 0; k < 16; k++) {
            float4 aA = *(const float4*)&As[cur][k][ty * 4];
            float4 aB = *(const float4*)&As[cur][k][64 + ty * 4];
            ulonglong2 bA = *(const ulonglong2*)&Bs[cur][k][tx * 4];
            ulonglong2 bB = *(const ulonglong2*)&Bs[cur][k][64 + tx * 4];
            unsigned long long b2[4] = { bA.x, bA.y, bB.x, bB.y };
            float a_[8] = { aA.x, aA.y, aA.z, aA.w, aB.x, aB.y, aB.z, aB.w };
            #pragma unroll
            for (int i = 0; i < 8; i++) {
                unsigned long long a2 = pack2(a_[i], a_[i]);
                #pragma unroll
                for (int j = 0; j < 4; j++) ffma2(acc[i][j], a2, b2[j]);
            }
        }
        if (more) {
            const int nb = cur ^ 1;
            As[nb][aq * 4 + 0][arow0] = pa0.x; As[nb][aq * 4 + 1][arow0] = pa0.y;
            As[nb][aq * 4 + 2][arow0] = pa0.z; As[nb][aq * 4 + 3][arow0] = pa0.w;
            As[nb][aq * 4 + 0][arow0 + 64] = pa1.x; As[nb][aq * 4 + 1][arow0 + 64] = pa1.y;
            As[nb][aq * 4 + 2][arow0 + 64] = pa1.z; As[nb][aq * 4 + 3][arow0 + 64] = pa1.w;
            *(float4*)&Bs[nb][brow0][bq * 4] = pb0;
            *(float4*)&Bs[nb][brow0 + 8][bq * 4] = pb1;
            __syncthreads();
        }
    }

    // epilogue
    #pragma unroll
    for (int i = 0; i < 8; i++) {
        int r = (i < 4) ? (ty * 4 + i) : (64 + ty * 4 + (i - 4));
        size_t crow = (size_t)(m0 + r) * N;
        #pragma unroll
        for (int j = 0; j < 4; j++) {
            int c = n0 + ((j < 2) ? (tx * 4 + j * 2) : (64 + tx * 4 + (j - 2) * 2));
            float2 v = unpack2(acc[i][j]);
            v.x += bias[c]; v.y += bias[c + 1];
            if (relu) { v.x = fmaxf(v.x, 0.f); v.y = fmaxf(v.y, 0.f); }
            *(float2*)&Cmat[crow + c] = v;
        }
    }
}

// ---------------- persistent GRU layer: 1 launch runs all T steps ----------------
// grid = 128 CTAs (all co-resident on 148 SMs), 256 threads.
// W slice [256][96] lives in dynamic smem for the whole layer.
// mode 0: hprev/hout walk hseq (saves full sequence).
// mode 1: ping-pong pb0/pb1 (final h in pb0 since T even).
__global__ __launch_bounds__(256, 1) void gru_layer(
    const float* __restrict__ gi,    // [T,B,3H] with b_ih + b_hh(r,z) folded
    const float* __restrict__ wpack, // [8][256][96]
    const float* __restrict__ bhh,   // original b_hh (n-gate slice used)
    float* __restrict__ hseq,
    float* __restrict__ pb0, float* __restrict__ pb1,
    int mode)
{
    extern __shared__ float sm[];
    float* Wsm = sm;                       // [256][96]
    float* HsB = sm + 256 * 96;            // [2][16][68]

    const int bid = blockIdx.x;
    const int nblk = bid & 7;
    const int b0 = (bid >> 3) << 6;
    const int n0 = nblk << 5;
    const int tid = threadIdx.x;
    const int tx = tid & 15, ty = tid >> 4;
    const int hr = tid >> 2, hq = tid & 3;

    // load W slice once (contiguous 98KB per nblk)
    {
        const float4* ws = (const float4*)(wpack + (size_t)nblk * 256 * 96);
        float4* wd = (float4*)Wsm;
        #pragma unroll 4
        for (int i = tid; i < 256 * 96 / 4; i += 256) wd[i] = ws[i];
    }
    __syncthreads();

    const int nn0 = n0 + tx * 2;
    const float2 bn2 = *(const float2*)&bhh[2 * Hn + nn0];

    for (int t = 0; t < Tn; t++) {
        const float* hprev; float* hout;
        if (mode == 0) {
            hprev = hseq + (size_t)(t - 1) * (Bn * Hn);
            hout  = hseq + (size_t)t * (Bn * Hn);
        } else {
            hprev = (t & 1) ? pb1 : pb0;
            hout  = (t & 1) ? pb0 : pb1;
        }

        if (t > 0) grid_barrier();   // step t-1 stores visible chip-wide

        // hoisted epilogue loads (overlap DRAM latency with GEMM)
        float2 gr[4], gz[4], gn[4], hp2[4];
        #pragma unroll
        for (int i = 0; i < 4; i++) {
            int b = b0 + ty * 4 + i;
            const float* gp = gi + ((size_t)t * Bn + b) * (3 * Hn);
            gr[i] = *(const float2*)(gp + nn0);
            gz[i] = *(const float2*)(gp + Hn + nn0);
            gn[i] = *(const float2*)(gp + 2 * Hn + nn0);
            hp2[i] = make_float2(0.f, 0.f);
            if (t > 0) hp2[i] = *(const float2*)(hprev + (size_t)b * Hn + nn0); // own columns: L1-coherent
        }

        unsigned long long accr[4], accz[4], accn[4];
        #pragma unroll
        for (int i = 0; i < 4; i++) { accr[i] = 0ull; accz[i] = 0ull; accn[i] = 0ull; }

        if (t > 0) {
            const float* Hp = hprev + (size_t)(b0 + hr) * Hn + (hq << 2);
            float4 ph = __ldcg((const float4*)Hp);   // cross-SM data: bypass L1

            float* H0 = HsB;
            H0[(hq * 4 + 0) * 68 + hr] = ph.x; H0[(hq * 4 + 1) * 68 + hr] = ph.y;
            H0[(hq * 4 + 2) * 68 + hr] = ph.z; H0[(hq * 4 + 3) * 68 + hr] = ph.w;
            __syncthreads();

            for (int it = 0; it < 16; ++it) {
                const int cur = it & 1;
                const bool more = it < 15;
                if (more) ph = __ldcg((const float4*)(Hp + ((it + 1) << 4)));

                const float* Hc = HsB + cur * (16 * 68);
                const float* Wb = Wsm + (it << 4) * 96;
                #pragma unroll
                for (int k = 0; k < 16; k++) {
                    float4 a4 = *(const float4*)(Hc + k * 68 + ty * 4);
                    const float* wk = Wb + k * 96;
                    unsigned long long br = *(const unsigned long long*)(wk + tx * 2);
                    unsigned long long bz = *(const unsigned long long*)(wk + 32 + tx * 2);
                    unsigned long long bn = *(const unsigned long long*)(wk + 64 + tx * 2);
                    float a_[4] = { a4.x, a4.y, a4.z, a4.w };
                    #pragma unroll
                    for (int i = 0; i < 4; i++) {
                        unsigned long long a2 = pack2(a_[i], a_[i]);
                        ffma2(accr[i], a2, br);
                        ffma2(accz[i], a2, bz);
                        ffma2(accn[i], a2, bn);
                    }
                }
                if (more) {
                    float* Hn_ = HsB + (cur ^ 1) * (16 * 68);
                    Hn_[(hq * 4 + 0) * 68 + hr] = ph.x; Hn_[(hq * 4 + 1) * 68 + hr] = ph.y;
                    Hn_[(hq * 4 + 2) * 68 + hr] = ph.z; Hn_[(hq * 4 + 3) * 68 + hr] = ph.w;
                    __syncthreads();
                }
            }
        }

        // gate math epilogue
        #pragma unroll
        for (int i = 0; i < 4; i++) {
            int b = b0 + ty * 4 + i;
            float2 r2 = unpack2(accr[i]), z2 = unpack2(accz[i]), n2 = unpack2(accn[i]);
            float rr[2] = { r2.x, r2.y }, zz[2] = { z2.x, z2.y }, nv[2] = { n2.x, n2.y };
            float grv[2] = { gr[i].x, gr[i].y }, gzv[2] = { gz[i].x, gz[i].y }, gnv[2] = { gn[i].x, gn[i].y };
            float bnn[2] = { bn2.x, bn2.y }, hpv[2] = { hp2[i].x, hp2[i].y };
            float outv[2];
            #pragma unroll
            for (int jj = 0; jj < 2; jj++) {
                float r = __fdividef(1.f, 1.f + __expf(-(grv[jj] + rr[jj])));
                float z = __fdividef(1.f, 1.f + __expf(-(gzv[jj] + zz[jj])));
                float a = gnv[jj] + r * (nv[jj] + bnn[jj]);
                float e = __expf(2.f * a);
                float nn = 1.f - __fdividef(2.f, e + 1.f);
                outv[jj] = (1.f - z) * nn + z * hpv[jj];
            }
            *(float2*)&hout[(size_t)b * Hn + nn0] = make_float2(outv[0], outv[1]);
        }
    }
}

// ---------------- soft cluster assignment q (Student-t, alpha=1) ----------------
__global__ __launch_bounds__(256) void qkernel(
    const float* __restrict__ z, const float* __restrict__ centers, float* __restrict__ q)
{
    __shared__ float cs[Kn * Hn];
    for (int i = threadIdx.x; i < Kn * Hn; i += 256) cs[i] = centers[i];
    __syncthreads();
    int warp = threadIdx.x >> 5, lane = threadIdx.x & 31;
    int b = blockIdx.x * 8 + warp;
    const float* zr = z + (size_t)b * Hn;
    float zv[8];
    #pragma unroll
    for (int i = 0; i < 8; i++) zv[i] = zr[lane + i * 32];
    float qk[Kn]; float s = 0.f;
    #pragma unroll
    for (int k = 0; k < Kn; k++) {
        float d2 = 0.f;
        #pragma unroll
        for (int i = 0; i < 8; i++) {
            float d = zv[i] - cs[k * Hn + lane + i * 32];
            d2 = fmaf(d, d, d2);
        }
        #pragma unroll
        for (int o = 16; o; o >>= 1) d2 += __shfl_xor_sync(0xffffffffu, d2, o);
        qk[k] = 1.f / (1.f + d2);
        s += qk[k];
    }
    if (lane == 0) {
        float inv = 1.f / s;
        #pragma unroll
        for (int k = 0; k < Kn; k++) q[b * Kn + k] = qk[k] * inv;
    }
}

// ---------------- final: logits + q-weighted combine ----------------
__global__ __launch_bounds__(256) void expert_out(
    const float* __restrict__ h2,  // [K,B,E2]
    const float* __restrict__ W3,  // [K,C,E2]
    const float* __restrict__ b3,  // [K,C]
    const float* __restrict__ q,   // [B,K]
    float* __restrict__ out)       // [B,C]
{
    int warp = threadIdx.x >> 5, lane = threadIdx.x & 31;
    int b = blockIdx.x * 8 + warp;
    float p0 = 0.f, p1 = 0.f;
    #pragma unroll
    for (int k = 0; k < Kn; k++) {
        const float* hr = h2 + ((size_t)k * Bn + b) * E2n;
        const float* w0 = W3 + (size_t)(k * 2 + 0) * E2n;
        const float* w1 = W3 + (size_t)(k * 2 + 1) * E2n;
        float d0 = 0.f, d1 = 0.f;
        #pragma unroll
        for (int i = 0; i < 8; i++) {
            float hv = hr[lane + i * 32];
            d0 = fmaf(hv, w0[lane + i * 32], d0);
            d1 = fmaf(hv, w1[lane + i * 32], d1);
        }
        #pragma unroll
        for (int o = 16; o; o >>= 1) {
            d0 += __shfl_xor_sync(0xffffffffu, d0, o);
            d1 += __shfl_xor_sync(0xffffffffu, d1, o);
        }
        float qv = q[b * Kn + k];
        p0 += qv * (d0 + b3[k * 2 + 0]);
        p1 += qv * (d1 + b3[k * 2 + 1]);
    }
    if (lane == 0) { out[b * 2 + 0] = p0; out[b * 2 + 1] = p1; }
}

// ---------------- launch ----------------
extern "C" void kernel_launch(void* const* d_in, const int* in_sizes, int n_in,
                              void* d_out, int out_size)
{
    const float* x      = (const float*)d_in[0];
    const float* W_ih0  = (const float*)d_in[1];
    const float* W_hh0  = (const float*)d_in[2];
    const float* b_ih0  = (const float*)d_in[3];
    const float* b_hh0  = (const float*)d_in[4];
    const float* W_ih1  = (const float*)d_in[5];
    const float* W_hh1  = (const float*)d_in[6];
    const float* b_ih1  = (const float*)d_in[7];
    const float* b_hh1  = (const float*)d_in[8];
    const float* cc     = (const float*)d_in[9];
    const float* eW1    = (const float*)d_in[10];
    const float* eb1    = (const float*)d_in[11];
    const float* eW2    = (const float*)d_in[12];
    const float* eb2    = (const float*)d_in[13];
    const float* eW3    = (const float*)d_in[14];
    const float* eb3    = (const float*)d_in[15];
    float* out = (float*)d_out;

    float *gi, *hseq, *hb0, *hb1, *q, *wih0, *wih1, *wp0, *wp1, *bs0, *bs1, *we1, *we2, *h1, *h2;
    cudaGetSymbolAddress((void**)&gi,   g_gi);
    cudaGetSymbolAddress((void**)&hseq, g_hseq);
    cudaGetSymbolAddress((void**)&hb0,  g_hbuf0);
    cudaGetSymbolAddress((void**)&hb1,  g_hbuf1);
    cudaGetSymbolAddress((void**)&q,    g_q);
    cudaGetSymbolAddress((void**)&wih0, g_Wt_ih0);
    cudaGetSymbolAddress((void**)&wih1, g_Wt_ih1);
    cudaGetSymbolAddress((void**)&wp0,  g_wp0);
    cudaGetSymbolAddress((void**)&wp1,  g_wp1);
    cudaGetSymbolAddress((void**)&bs0,  g_bsum0);
    cudaGetSymbolAddress((void**)&bs1,  g_bsum1);
    cudaGetSymbolAddress((void**)&we1,  g_Wt_e1);
    cudaGetSymbolAddress((void**)&we2,  g_Wt_e2);
    cudaGetSymbolAddress((void**)&h1,   g_h1);
    cudaGetSymbolAddress((void**)&h2,   g_h2);

    // allow 107KB dynamic smem for the persistent GRU kernel
    static int smem_set = 0;
    const int SMEM_GRU = (256 * 96 + 2 * 16 * 68) * 4;  // 107008 B
    if (!smem_set) {
        cudaFuncSetAttribute(gru_layer, cudaFuncAttributeMaxDynamicSharedMemorySize, SMEM_GRU);
        smem_set = 1;
    }

    // ---- launch 1: all transposes fused ----
    TJobs js;
    js.j[0] = { W_ih0, wih0, 3 * Hn, In,  In  / 32, (3 * Hn / 32) * (In  / 32), 0 };
    js.j[1] = { W_ih1, wih1, 3 * Hn, Hn,  Hn  / 32, (3 * Hn / 32) * (Hn  / 32), 0 };
    js.j[2] = { eW1,   we1,  E1n,    Hn,  Hn  / 32, (E1n / 32) * (Hn  / 32), 0 };
    js.j[3] = { eW2,   we2,  E2n,    E1n, E1n / 32, (E2n / 32) * (E1n / 32), 0 };
    js.j[1].off = js.j[0].off + js.j[0].tpb;
    js.j[2].off = js.j[1].off + js.j[1].tpb;
    js.j[3].off = js.j[2].off + js.j[2].tpb * Kn;
    int totalTiles = js.j[3].off + js.j[3].tpb * Kn;
    transpose_all<<<totalTiles, dim3(32, 8)>>>(js);

    // ---- launch 2: pack W_hh for both layers ----
    pack_whh<<<dim3(8, 8, 2), 256>>>(W_hh0, W_hh1, wp0, wp1);

    // ---- launch 3: fold b_hh(r,z) into gi bias ----
    bias_combine<<<1, 3 * Hn>>>(b_ih0, b_hh0, b_ih1, b_hh1, bs0, bs1);

    const int M0 = Tn * Bn;  // 131072

    // ---- gi0 = x @ W_ih0^T + bsum0, stored [T,B,3H] ----
    gemm128<<<dim3(3 * Hn / 128, M0 / 128, 1), 256>>>(
        x, wih0, bs0, gi, M0, 3 * Hn, In, In, /*amode=*/1, /*relu=*/0, 0, 0, 0, 0);

    // ---- layer-0 recurrence: ONE persistent launch ----
    gru_layer<<<NCTA, 256, SMEM_GRU>>>(gi, wp0, b_hh0, hseq, nullptr, nullptr, 0);

    // ---- gi1 = h_l0 @ W_ih1^T + bsum1 (reuse gi buffer) ----
    gemm128<<<dim3(3 * Hn / 128, M0 / 128, 1), 256>>>(
        hseq, wih1, bs1, gi, M0, 3 * Hn, Hn, Hn, 0, 0, 0, 0, 0, 0);

    // ---- layer-1 recurrence: ONE persistent launch (final h in hb0) ----
    gru_layer<<<NCTA, 256, SMEM_GRU>>>(gi, wp1, b_hh1, nullptr, hb0, hb1, 1);

    // ---- q [B,K] ----
    qkernel<<<Bn / 8, 256>>>(hb0, cc, q);

    // ---- experts (batched over K in grid.z) ----
    gemm128<<<dim3(E1n / 128, Bn / 128, Kn), 256>>>(
        hb0, we1, eb1, h1, Bn, E1n, Hn, Hn, 0, /*relu=*/1,
        0, (long long)Hn * E1n, E1n, (long long)Bn * E1n);
    gemm128<<<dim3(E2n / 128, Bn / 128, Kn), 256>>>(
        h1, we2, eb2, h2, Bn, E2n, E1n, E1n, 0, /*relu=*/1,
        (long long)Bn * E1n, (long long)E1n * E2n, E2n, (long long)Bn * E2n);

    // ---- logits + q-weighted combine -> out [B,C] ----
    expert_out<<<Bn / 8, 256>>>(h2, eW3, eb3, q, out);
}

// round 5
// speedup vs baseline: 1.5548x; 1.0717x over previous
#include <cuda_runtime.h>
#include <math.h>

// Problem constants
#define Tn 128
#define Bn 1024
#define In 128
#define Hn 256
#define Kn 8
#define E1n 512
#define E2n 256
#define NCTA 128
#define NGRP 16

// ---------------- device scratch (no allocations allowed) ----------------
__device__ __align__(256) float g_gi[(size_t)Tn * Bn * 3 * Hn];
__device__ __align__(256) float g_hseq[(size_t)Tn * Bn * Hn];
__device__ __align__(256) float g_hbuf0[Bn * Hn];
__device__ __align__(256) float g_hbuf1[Bn * Hn];
__device__ __align__(256) float g_q[Bn * Kn];
__device__ __align__(256) float g_Wt_ih0[In * 3 * Hn];
__device__ __align__(256) float g_Wt_ih1[Hn * 3 * Hn];
__device__ __align__(256) float g_wp0[8 * Hn * 96];
__device__ __align__(256) float g_wp1[8 * Hn * 96];
__device__ __align__(256) float g_bsum0[3 * Hn];
__device__ __align__(256) float g_bsum1[3 * Hn];
__device__ __align__(256) float g_Wt_e1[Kn * Hn * E1n];
__device__ __align__(256) float g_Wt_e2[Kn * E1n * E2n];
__device__ __align__(256) float g_h1[(size_t)Kn * Bn * E1n];
__device__ __align__(256) float g_h2[(size_t)Kn * Bn * E2n];

// per-group monotonic barrier counters (zero-init; reset at layer end)
__device__ __align__(256) unsigned g_grp_cnt[NGRP * 32];  // 128B stride per group

// ---------------- f32x2 packed math helpers (Blackwell FFMA2) ----------------
__device__ __forceinline__ unsigned long long pack2(float x, float y) {
    unsigned long long r;
    asm("mov.b64 %0, {%1, %2};" : "=l"(r) : "f"(x), "f"(y));
    return r;
}
__device__ __forceinline__ void ffma2(unsigned long long& d, unsigned long long a, unsigned long long b) {
    asm("fma.rn.f32x2 %0, %1, %2, %0;" : "+l"(d) : "l"(a), "l"(b));
}
__device__ __forceinline__ float2 unpack2(unsigned long long v) {
    float2 f;
    asm("mov.b64 {%0, %1}, %2;" : "=f"(f.x), "=f"(f.y) : "l"(v));
    return f;
}
__device__ __forceinline__ unsigned ld_acq_gpu(const unsigned* p) {
    unsigned v;
    asm volatile("ld.acquire.gpu.global.u32 %0, [%1];" : "=r"(v) : "l"(p) : "memory");
    return v;
}

// ---------------- fused transpose (all weight transposes in ONE launch) ----------------
struct TJob { const float* in; float* out; int R, C, tC, tpb, off; };
struct TJobs { TJob j[4]; };

__global__ void transpose_all(TJobs js)
{
    __shared__ float tile[32][33];
    int bx = blockIdx.x;
    int ji = 0;
    if (bx >= js.j[1].off) ji = 1;
    if (bx >= js.j[2].off) ji = 2;
    if (bx >= js.j[3].off) ji = 3;
    TJob jb = js.j[ji];
    int local = bx - jb.off;
    int batch = local / jb.tpb;
    int rem = local - batch * jb.tpb;
    int cIdx = rem % jb.tC, rIdx = rem / jb.tC;
    size_t boff = (size_t)batch * jb.R * jb.C;
    int c0 = cIdx * 32, r0 = rIdx * 32;
    int tx = threadIdx.x, ty = threadIdx.y;
    #pragma unroll
    for (int i = ty; i < 32; i += 8)
        tile[i][tx] = jb.in[boff + (size_t)(r0 + i) * jb.C + c0 + tx];
    __syncthreads();
    #pragma unroll
    for (int i = ty; i < 32; i += 8)
        jb.out[boff + (size_t)(c0 + i) * jb.R + r0 + tx] = tile[tx][i];
}

// ---------------- pack W_hh into per-nblk contiguous [nblk][k][96] ----------------
__global__ void pack_whh(const float* __restrict__ W0, const float* __restrict__ W1,
                         float* __restrict__ P0, float* __restrict__ P1)
{
    const float* W = blockIdx.z ? W1 : W0;
    float* P = blockIdx.z ? P1 : P0;
    int nblk = blockIdx.x, k0 = blockIdx.y * 32;
    __shared__ float tile[96][33];
    int tx = threadIdx.x & 31, ty = threadIdx.x >> 5;  // 32 x 8
    for (int j = ty; j < 96; j += 8) {
        int row = (j >> 5) * Hn + nblk * 32 + (j & 31);
        tile[j][tx] = W[(size_t)row * Hn + k0 + tx];
    }
    __syncthreads();
    for (int idx = threadIdx.x; idx < 32 * 96; idx += 256) {
        int kk = idx / 96, c = idx - kk * 96;
        P[((size_t)nblk * Hn + k0 + kk) * 96 + c] = tile[c][kk];
    }
}

// ---------------- bias combine: fold b_hh (r,z gates) into gi bias ----------------
__global__ void bias_combine(const float* bih0, const float* bhh0,
                             const float* bih1, const float* bhh1,
                             float* o0, float* o1)
{
    int i = threadIdx.x;  // 768
    o0[i] = bih0[i] + (i < 2 * Hn ? bhh0[i] : 0.f);
    o1[i] = bih1[i] + (i < 2 * Hn ? bhh1[i] : 0.f);
}

// ---------------- double-buffered 128x128x16 fp32x2 GEMM: C = act(A @ Bt + bias) ----------------
__global__ __launch_bounds__(256, 2) void gemm128(
    const float* __restrict__ A, const float* __restrict__ Bt,
    const float* __restrict__ bias, float* __restrict__ Cmat,
    int M, int N, int K, int lda, int amode, int relu,
    long long sA, long long sB, long long sBias, long long sC)
{
    const int bz = blockIdx.z;
    A    += (size_t)sA * bz;
    Bt   += (size_t)sB * bz;
    bias += (size_t)sBias * bz;
    Cmat += (size_t)sC * bz;
    const int n0 = blockIdx.x * 128;
    const int m0 = blockIdx.y * 128;

    __shared__ float As[2][16][132];
    __shared__ float Bs[2][16][128];

    const int tid = threadIdx.x;
    const int tx = tid & 15, ty = tid >> 4;
    const int arow0 = tid >> 2, aq = tid & 3;
    const int brow0 = tid >> 5, bq = tid & 31;

    size_t ab0, ab1;
    { int m = m0 + arow0;
      ab0 = (amode == 0) ? (size_t)m * lda
                         : ((size_t)(m & (Bn - 1)) * Tn + (m >> 10)) * (size_t)lda; }
    { int m = m0 + arow0 + 64;
      ab1 = (amode == 0) ? (size_t)m * lda
                         : ((size_t)(m & (Bn - 1)) * Tn + (m >> 10)) * (size_t)lda; }
    const float* Ap0 = A + ab0 + aq * 4;
    const float* Ap1 = A + ab1 + aq * 4;
    const float* Bp0 = Bt + (size_t)brow0 * N + n0 + bq * 4;
    const float* Bp1 = Bt + (size_t)(brow0 + 8) * N + n0 + bq * 4;

    unsigned long long acc[8][4];
    #pragma unroll
    for (int i = 0; i < 8; i++)
        #pragma unroll
        for (int j = 0; j < 4; j++) acc[i][j] = 0ull;

    // prologue: tile 0 -> buf 0
    float4 pa0 = *(const float4*)(Ap0);
    float4 pa1 = *(const float4*)(Ap1);
    float4 pb0 = *(const float4*)(Bp0);
    float4 pb1 = *(const float4*)(Bp1);
    As[0][aq * 4 + 0][arow0] = pa0.x; As[0][aq * 4 + 1][arow0] = pa0.y;
    As[0][aq * 4 + 2][arow0] = pa0.z; As[0][aq * 4 + 3][arow0] = pa0.w;
    As[0][aq * 4 + 0][arow0 + 64] = pa1.x; As[0][aq * 4 + 1][arow0 + 64] = pa1.y;
    As[0][aq * 4 + 2][arow0 + 64] = pa1.z; As[0][aq * 4 + 3][arow0 + 64] = pa1.w;
    *(float4*)&Bs[0][brow0][bq * 4] = pb0;
    *(float4*)&Bs[0][brow0 + 8][bq * 4] = pb1;
    __syncthreads();

    const int nit = K >> 4;
    for (int it = 0; it < nit; ++it) {
        const int cur = it & 1;
        const bool more = (it + 1) < nit;
        if (more) {
            const int k0 = (it + 1) << 4;
            pa0 = *(const float4*)(Ap0 + k0);
            pa1 = *(const float4*)(Ap1 + k0);
            pb0 = *(const float4*)(Bp0 + (size_t)k0 * N);
            pb1 = *(const float4*)(Bp1 + (size_t)k0 * N);
        }
        #pragma unroll
        for (int k = 0; k < 16; k++) {
            float4 aA = *(const float4*)&As[cur][k][ty * 4];
            float4 aB = *(const float4*)&As[cur][k][64 + ty * 4];
            ulonglong2 bA = *(const ulonglong2*)&Bs[cur][k][tx * 4];
            ulonglong2 bB = *(const ulonglong2*)&Bs[cur][k][64 + tx * 4];
            unsigned long long b2[4] = { bA.x, bA.y, bB.x, bB.y };
            float a_[8] = { aA.x, aA.y, aA.z, aA.w, aB.x, aB.y, aB.z, aB.w };
            #pragma unroll
            for (int i = 0; i < 8; i++) {
                unsigned long long a2 = pack2(a_[i], a_[i]);
                #pragma unroll
                for (int j = 0; j < 4; j++) ffma2(acc[i][j], a2, b2[j]);
            }
        }
        if (more) {
            const int nb = cur ^ 1;
            As[nb][aq * 4 + 0][arow0] = pa0.x; As[nb][aq * 4 + 1][arow0] = pa0.y;
            As[nb][aq * 4 + 2][arow0] = pa0.z; As[nb][aq * 4 + 3][arow0] = pa0.w;
            As[nb][aq * 4 + 0][arow0 + 64] = pa1.x; As[nb][aq * 4 + 1][arow0 + 64] = pa1.y;
            As[nb][aq * 4 + 2][arow0 + 64] = pa1.z; As[nb][aq * 4 + 3][arow0 + 64] = pa1.w;
            *(float4*)&Bs[nb][brow0][bq * 4] = pb0;
            *(float4*)&Bs[nb][brow0 + 8][bq * 4] = pb1;
            __syncthreads();
        }
    }

    // epilogue
    #pragma unroll
    for (int i = 0; i < 8; i++) {
        int r = (i < 4) ? (ty * 4 + i) : (64 + ty * 4 + (i - 4));
        size_t crow = (size_t)(m0 + r) * N;
        #pragma unroll
        for (int j = 0; j < 4; j++) {
            int c = n0 + ((j < 2) ? (tx * 4 + j * 2) : (64 + tx * 4 + (j - 2) * 2));
            float2 v = unpack2(acc[i][j]);
            v.x += bias[c]; v.y += bias[c + 1];
            if (relu) { v.x = fmaxf(v.x, 0.f); v.y = fmaxf(v.y, 0.f); }
            *(float2*)&Cmat[crow + c] = v;
        }
    }
}

// ---------------- persistent GRU layer with per-group (8-CTA) barriers ----------------
// grid = 128 CTAs, 256 threads. bid = bg*8 + nblk; group = batch group bg.
// Steps of different groups drift independently (no global coupling).
__global__ __launch_bounds__(256, 1) void gru_layer(
    const float* __restrict__ gi,    // [T,B,3H] with b_ih + b_hh(r,z) folded
    const float* __restrict__ wpack, // [8][256][96]
    const float* __restrict__ bhh,   // original b_hh (n-gate slice used)
    float* __restrict__ hseq,
    float* __restrict__ pb0, float* __restrict__ pb1,
    int mode)
{
    extern __shared__ float sm[];
    float* Wsm = sm;                       // [256][96]
    float* HsB = sm + 256 * 96;            // [2][16][68]

    const int bid = blockIdx.x;
    const int nblk = bid & 7;
    const int b0 = (bid >> 3) << 6;
    const int n0 = nblk << 5;
    const int tid = threadIdx.x;
    const int tx = tid & 15, ty = tid >> 4;
    const int hr = tid >> 2, hq = tid & 3;
    unsigned* cnt = g_grp_cnt + (bid >> 3) * 32;

    // load W slice once (contiguous 98KB per nblk)
    {
        const float4* ws = (const float4*)(wpack + (size_t)nblk * 256 * 96);
        float4* wd = (float4*)Wsm;
        #pragma unroll 4
        for (int i = tid; i < 256 * 96 / 4; i += 256) wd[i] = ws[i];
    }
    __syncthreads();

    const int nn0 = n0 + tx * 2;
    const float2 bn2 = *(const float2*)&bhh[2 * Hn + nn0];

    for (int t = 0; t < Tn; t++) {
        const float* hprev; float* hout;
        if (mode == 0) {
            hprev = hseq + (size_t)(t - 1) * (Bn * Hn);
            hout  = hseq + (size_t)t * (Bn * Hn);
        } else {
            hprev = (t & 1) ? pb1 : pb0;
            hout  = (t & 1) ? pb0 : pb1;
        }

        // loads independent of peer CTAs: issue BEFORE the barrier wait
        float2 gr[4], gz[4], gn[4], hp2[4];
        #pragma unroll
        for (int i = 0; i < 4; i++) {
            int b = b0 + ty * 4 + i;
            const float* gp = gi + ((size_t)t * Bn + b) * (3 * Hn);
            gr[i] = *(const float2*)(gp + nn0);
            gz[i] = *(const float2*)(gp + Hn + nn0);
            gn[i] = *(const float2*)(gp + 2 * Hn + nn0);
            hp2[i] = make_float2(0.f, 0.f);
            if (t > 0) hp2[i] = *(const float2*)(hprev + (size_t)b * Hn + nn0); // own data
        }

        // group barrier: wait until all 8 CTAs of this batch group finished step t-1
        if (t > 0) {
            __syncthreads();
            if (tid == 0) {
                while (ld_acq_gpu(cnt) < (unsigned)(8 * t)) {}
            }
            __syncthreads();
        }

        unsigned long long accr[4], accz[4], accn[4];
        #pragma unroll
        for (int i = 0; i < 4; i++) { accr[i] = 0ull; accz[i] = 0ull; accn[i] = 0ull; }

        if (t > 0) {
            const float* Hp = hprev + (size_t)(b0 + hr) * Hn + (hq << 2);
            float4 ph = __ldcg((const float4*)Hp);   // cross-SM data: bypass L1

            float* H0 = HsB;
            H0[(hq * 4 + 0) * 68 + hr] = ph.x; H0[(hq * 4 + 1) * 68 + hr] = ph.y;
            H0[(hq * 4 + 2) * 68 + hr] = ph.z; H0[(hq * 4 + 3) * 68 + hr] = ph.w;
            __syncthreads();

            for (int it = 0; it < 16; ++it) {
                const int cur = it & 1;
                const bool more = it < 15;
                if (more) ph = __ldcg((const float4*)(Hp + ((it + 1) << 4)));

                const float* Hc = HsB + cur * (16 * 68);
                const float* Wb = Wsm + (it << 4) * 96;
                #pragma unroll
                for (int k = 0; k < 16; k++) {
                    float4 a4 = *(const float4*)(Hc + k * 68 + ty * 4);
                    const float* wk = Wb + k * 96;
                    unsigned long long br = *(const unsigned long long*)(wk + tx * 2);
                    unsigned long long bz = *(const unsigned long long*)(wk + 32 + tx * 2);
                    unsigned long long bn = *(const unsigned long long*)(wk + 64 + tx * 2);
                    float a_[4] = { a4.x, a4.y, a4.z, a4.w };
                    #pragma unroll
                    for (int i = 0; i < 4; i++) {
                        unsigned long long a2 = pack2(a_[i], a_[i]);
                        ffma2(accr[i], a2, br);
                        ffma2(accz[i], a2, bz);
                        ffma2(accn[i], a2, bn);
                    }
                }
                if (more) {
                    float* Hx = HsB + (cur ^ 1) * (16 * 68);
                    Hx[(hq * 4 + 0) * 68 + hr] = ph.x; Hx[(hq * 4 + 1) * 68 + hr] = ph.y;
                    Hx[(hq * 4 + 2) * 68 + hr] = ph.z; Hx[(hq * 4 + 3) * 68 + hr] = ph.w;
                    __syncthreads();
                }
            }
        }

        // gate math epilogue
        #pragma unroll
        for (int i = 0; i < 4; i++) {
            int b = b0 + ty * 4 + i;
            float2 r2 = unpack2(accr[i]), z2 = unpack2(accz[i]), n2 = unpack2(accn[i]);
            float rr[2] = { r2.x, r2.y }, zz[2] = { z2.x, z2.y }, nv[2] = { n2.x, n2.y };
            float grv[2] = { gr[i].x, gr[i].y }, gzv[2] = { gz[i].x, gz[i].y }, gnv[2] = { gn[i].x, gn[i].y };
            float bnn[2] = { bn2.x, bn2.y }, hpv[2] = { hp2[i].x, hp2[i].y };
            float outv[2];
            #pragma unroll
            for (int jj = 0; jj < 2; jj++) {
                float r = __fdividef(1.f, 1.f + __expf(-(grv[jj] + rr[jj])));
                float z = __fdividef(1.f, 1.f + __expf(-(gzv[jj] + zz[jj])));
                float a = gnv[jj] + r * (nv[jj] + bnn[jj]);
                float e = __expf(2.f * a);
                float nn = 1.f - __fdividef(2.f, e + 1.f);
                outv[jj] = (1.f - z) * nn + z * hpv[jj];
            }
            *(float2*)&hout[(size_t)b * Hn + nn0] = make_float2(outv[0], outv[1]);
        }

        // arrive: h(t) stores drained (threadfence), then bump group counter
        __syncthreads();
        if (tid == 0) {
            __threadfence();
            atomicAdd(cnt, 1u);
        }
    }

    // reset counter for next launch (after all 8 CTAs fully arrived)
    if (tid == 0 && nblk == 0) {
        while (ld_acq_gpu(cnt) < (unsigned)(8 * Tn)) {}
        atomicExch(cnt, 0u);
    }
}

// ---------------- soft cluster assignment q (Student-t, alpha=1) ----------------
__global__ __launch_bounds__(256) void qkernel(
    const float* __restrict__ z, const float* __restrict__ centers, float* __restrict__ q)
{
    __shared__ float cs[Kn * Hn];
    for (int i = threadIdx.x; i < Kn * Hn; i += 256) cs[i] = centers[i];
    __syncthreads();
    int warp = threadIdx.x >> 5, lane = threadIdx.x & 31;
    int b = blockIdx.x * 8 + warp;
    const float* zr = z + (size_t)b * Hn;
    float zv[8];
    #pragma unroll
    for (int i = 0; i < 8; i++) zv[i] = zr[lane + i * 32];
    float qk[Kn]; float s = 0.f;
    #pragma unroll
    for (int k = 0; k < Kn; k++) {
        float d2 = 0.f;
        #pragma unroll
        for (int i = 0; i < 8; i++) {
            float d = zv[i] - cs[k * Hn + lane + i * 32];
            d2 = fmaf(d, d, d2);
        }
        #pragma unroll
        for (int o = 16; o; o >>= 1) d2 += __shfl_xor_sync(0xffffffffu, d2, o);
        qk[k] = 1.f / (1.f + d2);
        s += qk[k];
    }
    if (lane == 0) {
        float inv = 1.f / s;
        #pragma unroll
        for (int k = 0; k < Kn; k++) q[b * Kn + k] = qk[k] * inv;
    }
}

// ---------------- final: logits + q-weighted combine ----------------
__global__ __launch_bounds__(256) void expert_out(
    const float* __restrict__ h2,  // [K,B,E2]
    const float* __restrict__ W3,  // [K,C,E2]
    const float* __restrict__ b3,  // [K,C]
    const float* __restrict__ q,   // [B,K]
    float* __restrict__ out)       // [B,C]
{
    int warp = threadIdx.x >> 5, lane = threadIdx.x & 31;
    int b = blockIdx.x * 8 + warp;
    float p0 = 0.f, p1 = 0.f;
    #pragma unroll
    for (int k = 0; k < Kn; k++) {
        const float* hr = h2 + ((size_t)k * Bn + b) * E2n;
        const float* w0 = W3 + (size_t)(k * 2 + 0) * E2n;
        const float* w1 = W3 + (size_t)(k * 2 + 1) * E2n;
        float d0 = 0.f, d1 = 0.f;
        #pragma unroll
        for (int i = 0; i < 8; i++) {
            float hv = hr[lane + i * 32];
            d0 = fmaf(hv, w0[lane + i * 32], d0);
            d1 = fmaf(hv, w1[lane + i * 32], d1);
        }
        #pragma unroll
        for (int o = 16; o; o >>= 1) {
            d0 += __shfl_xor_sync(0xffffffffu, d0, o);
            d1 += __shfl_xor_sync(0xffffffffu, d1, o);
        }
        float qv = q[b * Kn + k];
        p0 += qv * (d0 + b3[k * 2 + 0]);
        p1 += qv * (d1 + b3[k * 2 + 1]);
    }
    if (lane == 0) { out[b * 2 + 0] = p0; out[b * 2 + 1] = p1; }
}

// ---------------- launch ----------------
extern "C" void kernel_launch(void* const* d_in, const int* in_sizes, int n_in,
                              void* d_out, int out_size)
{
    const float* x      = (const float*)d_in[0];
    const float* W_ih0  = (const float*)d_in[1];
    const float* W_hh0  = (const float*)d_in[2];
    const float* b_ih0  = (const float*)d_in[3];
    const float* b_hh0  = (const float*)d_in[4];
    const float* W_ih1  = (const float*)d_in[5];
    const float* W_hh1  = (const float*)d_in[6];
    const float* b_ih1  = (const float*)d_in[7];
    const float* b_hh1  = (const float*)d_in[8];
    const float* cc     = (const float*)d_in[9];
    const float* eW1    = (const float*)d_in[10];
    const float* eb1    = (const float*)d_in[11];
    const float* eW2    = (const float*)d_in[12];
    const float* eb2    = (const float*)d_in[13];
    const float* eW3    = (const float*)d_in[14];
    const float* eb3    = (const float*)d_in[15];
    float* out = (float*)d_out;

    float *gi, *hseq, *hb0, *hb1, *q, *wih0, *wih1, *wp0, *wp1, *bs0, *bs1, *we1, *we2, *h1, *h2;
    cudaGetSymbolAddress((void**)&gi,   g_gi);
    cudaGetSymbolAddress((void**)&hseq, g_hseq);
    cudaGetSymbolAddress((void**)&hb0,  g_hbuf0);
    cudaGetSymbolAddress((void**)&hb1,  g_hbuf1);
    cudaGetSymbolAddress((void**)&q,    g_q);
    cudaGetSymbolAddress((void**)&wih0, g_Wt_ih0);
    cudaGetSymbolAddress((void**)&wih1, g_Wt_ih1);
    cudaGetSymbolAddress((void**)&wp0,  g_wp0);
    cudaGetSymbolAddress((void**)&wp1,  g_wp1);
    cudaGetSymbolAddress((void**)&bs0,  g_bsum0);
    cudaGetSymbolAddress((void**)&bs1,  g_bsum1);
    cudaGetSymbolAddress((void**)&we1,  g_Wt_e1);
    cudaGetSymbolAddress((void**)&we2,  g_Wt_e2);
    cudaGetSymbolAddress((void**)&h1,   g_h1);
    cudaGetSymbolAddress((void**)&h2,   g_h2);

    // allow 107KB dynamic smem for the persistent GRU kernel
    static int smem_set = 0;
    const int SMEM_GRU = (256 * 96 + 2 * 16 * 68) * 4;  // 107008 B
    if (!smem_set) {
        cudaFuncSetAttribute(gru_layer, cudaFuncAttributeMaxDynamicSharedMemorySize, SMEM_GRU);
        smem_set = 1;
    }

    // ---- launch 1: all transposes fused ----
    TJobs js;
    js.j[0] = { W_ih0, wih0, 3 * Hn, In,  In  / 32, (3 * Hn / 32) * (In  / 32), 0 };
    js.j[1] = { W_ih1, wih1, 3 * Hn, Hn,  Hn  / 32, (3 * Hn / 32) * (Hn  / 32), 0 };
    js.j[2] = { eW1,   we1,  E1n,    Hn,  Hn  / 32, (E1n / 32) * (Hn  / 32), 0 };
    js.j[3] = { eW2,   we2,  E2n,    E1n, E1n / 32, (E2n / 32) * (E1n / 32), 0 };
    js.j[1].off = js.j[0].off + js.j[0].tpb;
    js.j[2].off = js.j[1].off + js.j[1].tpb;
    js.j[3].off = js.j[2].off + js.j[2].tpb * Kn;
    int totalTiles = js.j[3].off + js.j[3].tpb * Kn;
    transpose_all<<<totalTiles, dim3(32, 8)>>>(js);

    // ---- launch 2: pack W_hh for both layers ----
    pack_whh<<<dim3(8, 8, 2), 256>>>(W_hh0, W_hh1, wp0, wp1);

    // ---- launch 3: fold b_hh(r,z) into gi bias ----
    bias_combine<<<1, 3 * Hn>>>(b_ih0, b_hh0, b_ih1, b_hh1, bs0, bs1);

    const int M0 = Tn * Bn;  // 131072

    // ---- gi0 = x @ W_ih0^T + bsum0, stored [T,B,3H] ----
    gemm128<<<dim3(3 * Hn / 128, M0 / 128, 1), 256>>>(
        x, wih0, bs0, gi, M0, 3 * Hn, In, In, /*amode=*/1, /*relu=*/0, 0, 0, 0, 0);

    // ---- layer-0 recurrence: ONE persistent launch ----
    gru_layer<<<NCTA, 256, SMEM_GRU>>>(gi, wp0, b_hh0, hseq, nullptr, nullptr, 0);

    // ---- gi1 = h_l0 @ W_ih1^T + bsum1 (reuse gi buffer) ----
    gemm128<<<dim3(3 * Hn / 128, M0 / 128, 1), 256>>>(
        hseq, wih1, bs1, gi, M0, 3 * Hn, Hn, Hn, 0, 0, 0, 0, 0, 0);

    // ---- layer-1 recurrence: ONE persistent launch (final h in hb0) ----
    gru_layer<<<NCTA, 256, SMEM_GRU>>>(gi, wp1, b_hh1, nullptr, hb0, hb1, 1);

    // ---- q [B,K] ----
    qkernel<<<Bn / 8, 256>>>(hb0, cc, q);

    // ---- experts (batched over K in grid.z) ----
    gemm128<<<dim3(E1n / 128, Bn / 128, Kn), 256>>>(
        hb0, we1, eb1, h1, Bn, E1n, Hn, Hn, 0, /*relu=*/1,
        0, (long long)Hn * E1n, E1n, (long long)Bn * E1n);
    gemm128<<<dim3(E2n / 128, Bn / 128, Kn), 256>>>(
        h1, we2, eb2, h2, Bn, E2n, E1n, E1n, 0, /*relu=*/1,
        (long long)Bn * E1n, (long long)E1n * E2n, E2n, (long long)Bn * E2n);

    // ---- logits + q-weighted combine -> out [B,C] ----
    expert_out<<<Bn / 8, 256>>>(h2, eW3, eb3, q, out);
}

// round 6
// speedup vs baseline: 1.8466x; 1.1877x over previous
#include <cuda_runtime.h>
#include <math.h>

// Problem constants
#define Tn 128
#define Bn 1024
#define In 128
#define Hn 256
#define Kn 8
#define E1n 512
#define E2n 256
#define NCTA 128
#define NGRP 16

// ---------------- device scratch (no allocations allowed) ----------------
__device__ __align__(256) float g_gi[(size_t)Tn * Bn * 3 * Hn];
__device__ __align__(256) float g_hseq[(size_t)Tn * Bn * Hn];
__device__ __align__(256) float g_hbuf0[Bn * Hn];
__device__ __align__(256) float g_hbuf1[Bn * Hn];
__device__ __align__(256) float g_q[Bn * Kn];
__device__ __align__(256) float g_Wt_ih0[In * 3 * Hn];
__device__ __align__(256) float g_Wt_ih1[Hn * 3 * Hn];
__device__ __align__(256) float g_wp0[8 * Hn * 96];
__device__ __align__(256) float g_wp1[8 * Hn * 96];
__device__ __align__(256) float g_bsum0[3 * Hn];
__device__ __align__(256) float g_bsum1[3 * Hn];
__device__ __align__(256) float g_Wt_e1[Kn * Hn * E1n];
__device__ __align__(256) float g_Wt_e2[Kn * E1n * E2n];
__device__ __align__(256) float g_h1[(size_t)Kn * Bn * E1n];
__device__ __align__(256) float g_h2[(size_t)Kn * Bn * E2n];

// per-group monotonic barrier counters (zero-init; reset at layer end)
__device__ __align__(256) unsigned g_grp_cnt[NGRP * 32];  // 128B stride per group

// ---------------- f32x2 packed math helpers (Blackwell FFMA2) ----------------
__device__ __forceinline__ unsigned long long pack2(float x, float y) {
    unsigned long long r;
    asm("mov.b64 %0, {%1, %2};" : "=l"(r) : "f"(x), "f"(y));
    return r;
}
__device__ __forceinline__ void ffma2(unsigned long long& d, unsigned long long a, unsigned long long b) {
    asm("fma.rn.f32x2 %0, %1, %2, %0;" : "+l"(d) : "l"(a), "l"(b));
}
__device__ __forceinline__ float2 unpack2(unsigned long long v) {
    float2 f;
    asm("mov.b64 {%0, %1}, %2;" : "=f"(f.x), "=f"(f.y) : "l"(v));
    return f;
}
__device__ __forceinline__ unsigned ld_acq_gpu(const unsigned* p) {
    unsigned v;
    asm volatile("ld.acquire.gpu.global.u32 %0, [%1];" : "=r"(v) : "l"(p) : "memory");
    return v;
}

// ---------------- tf32 mma helpers ----------------
__device__ __forceinline__ unsigned f2tf32(float x) {
    unsigned u;
    asm("cvt.rna.tf32.f32 %0, %1;" : "=r"(u) : "f"(x));
    return u;
}
__device__ __forceinline__ void mma_tf32(float* c, const unsigned* a, const unsigned* b) {
    asm volatile(
        "mma.sync.aligned.m16n8k8.row.col.f32.tf32.tf32.f32 "
        "{%0,%1,%2,%3}, {%4,%5,%6,%7}, {%8,%9}, {%0,%1,%2,%3};"
        : "+f"(c[0]), "+f"(c[1]), "+f"(c[2]), "+f"(c[3])
        : "r"(a[0]), "r"(a[1]), "r"(a[2]), "r"(a[3]), "r"(b[0]), "r"(b[1]));
}

// ---------------- fused transpose (all weight transposes in ONE launch) ----------------
struct TJob { const float* in; float* out; int R, C, tC, tpb, off; };
struct TJobs { TJob j[4]; };

__global__ void transpose_all(TJobs js)
{
    __shared__ float tile[32][33];
    int bx = blockIdx.x;
    int ji = 0;
    if (bx >= js.j[1].off) ji = 1;
    if (bx >= js.j[2].off) ji = 2;
    if (bx >= js.j[3].off) ji = 3;
    TJob jb = js.j[ji];
    int local = bx - jb.off;
    int batch = local / jb.tpb;
    int rem = local - batch * jb.tpb;
    int cIdx = rem % jb.tC, rIdx = rem / jb.tC;
    size_t boff = (size_t)batch * jb.R * jb.C;
    int c0 = cIdx * 32, r0 = rIdx * 32;
    int tx = threadIdx.x, ty = threadIdx.y;
    #pragma unroll
    for (int i = ty; i < 32; i += 8)
        tile[i][tx] = jb.in[boff + (size_t)(r0 + i) * jb.C + c0 + tx];
    __syncthreads();
    #pragma unroll
    for (int i = ty; i < 32; i += 8)
        jb.out[boff + (size_t)(c0 + i) * jb.R + r0 + tx] = tile[tx][i];
}

// ---------------- pack W_hh into per-nblk contiguous [nblk][k][96] ----------------
__global__ void pack_whh(const float* __restrict__ W0, const float* __restrict__ W1,
                         float* __restrict__ P0, float* __restrict__ P1)
{
    const float* W = blockIdx.z ? W1 : W0;
    float* P = blockIdx.z ? P1 : P0;
    int nblk = blockIdx.x, k0 = blockIdx.y * 32;
    __shared__ float tile[96][33];
    int tx = threadIdx.x & 31, ty = threadIdx.x >> 5;  // 32 x 8
    for (int j = ty; j < 96; j += 8) {
        int row = (j >> 5) * Hn + nblk * 32 + (j & 31);
        tile[j][tx] = W[(size_t)row * Hn + k0 + tx];
    }
    __syncthreads();
    for (int idx = threadIdx.x; idx < 32 * 96; idx += 256) {
        int kk = idx / 96, c = idx - kk * 96;
        P[((size_t)nblk * Hn + k0 + kk) * 96 + c] = tile[c][kk];
    }
}

// ---------------- bias combine: fold b_hh (r,z gates) into gi bias ----------------
__global__ void bias_combine(const float* bih0, const float* bhh0,
                             const float* bih1, const float* bhh1,
                             float* o0, float* o1)
{
    int i = threadIdx.x;  // 768
    o0[i] = bih0[i] + (i < 2 * Hn ? bhh0[i] : 0.f);
    o1[i] = bih1[i] + (i < 2 * Hn ? bhh1[i] : 0.f);
}

// ---------------- tf32 tensor-core GEMM: C = A @ Bt + bias (for gi GEMMs) ----------------
// 128x128 block tile, 8 warps (64x32 warp tiles), k-tile 16, double-buffered.
__global__ __launch_bounds__(256) void gemm_tf32(
    const float* __restrict__ A, const float* __restrict__ Bt,
    const float* __restrict__ bias, float* __restrict__ Cmat,
    int M, int N, int K, int lda, int amode)
{
    __shared__ float As[2][128][20];   // row-major A tile, pad 20 (16B-aligned rows)
    __shared__ float Bs[2][16][136];   // [k][n] tile, pad 136 (conflict-free frag loads)

    const int n0 = blockIdx.x * 128;
    const int m0 = blockIdx.y * 128;
    const int tid = threadIdx.x;
    const int lane = tid & 31, w = tid >> 5;
    const int wm0 = (w >> 2) * 64, wn0 = (w & 3) * 32;
    const int gid = lane >> 2, tig = lane & 3;   // groupID, threadID_in_group

    const int arow0 = tid >> 2, aq = tid & 3;
    const int brow0 = tid >> 5, bq = tid & 31;

    size_t ab0, ab1;
    { int m = m0 + arow0;
      ab0 = (amode == 0) ? (size_t)m * lda
                         : ((size_t)(m & (Bn - 1)) * Tn + (m >> 10)) * (size_t)lda; }
    { int m = m0 + arow0 + 64;
      ab1 = (amode == 0) ? (size_t)m * lda
                         : ((size_t)(m & (Bn - 1)) * Tn + (m >> 10)) * (size_t)lda; }
    const float* Ap0 = A + ab0 + aq * 4;
    const float* Ap1 = A + ab1 + aq * 4;
    const float* Bp0 = Bt + (size_t)brow0 * N + n0 + bq * 4;
    const float* Bp1 = Bt + (size_t)(brow0 + 8) * N + n0 + bq * 4;

    float c[4][4][4];
    #pragma unroll
    for (int mi = 0; mi < 4; mi++)
        #pragma unroll
        for (int ni = 0; ni < 4; ni++)
            #pragma unroll
            for (int r = 0; r < 4; r++) c[mi][ni][r] = 0.f;

    // prologue: tile 0 -> buf 0
    float4 pa0 = *(const float4*)(Ap0);
    float4 pa1 = *(const float4*)(Ap1);
    float4 pb0 = *(const float4*)(Bp0);
    float4 pb1 = *(const float4*)(Bp1);
    *(float4*)&As[0][arow0][aq * 4] = pa0;
    *(float4*)&As[0][arow0 + 64][aq * 4] = pa1;
    *(float4*)&Bs[0][brow0][bq * 4] = pb0;
    *(float4*)&Bs[0][brow0 + 8][bq * 4] = pb1;
    __syncthreads();

    const int nit = K >> 4;
    for (int it = 0; it < nit; ++it) {
        const int cur = it & 1;
        const bool more = (it + 1) < nit;
        if (more) {
            const int k0 = (it + 1) << 4;
            pa0 = *(const float4*)(Ap0 + k0);
            pa1 = *(const float4*)(Ap1 + k0);
            pb0 = *(const float4*)(Bp0 + (size_t)k0 * N);
            pb1 = *(const float4*)(Bp1 + (size_t)k0 * N);
        }
        #pragma unroll
        for (int ks = 0; ks < 2; ks++) {
            const int ac = ks * 8 + tig;
            unsigned af[4][4];
            #pragma unroll
            for (int mi = 0; mi < 4; mi++) {
                const int rb = wm0 + mi * 16 + gid;
                af[mi][0] = f2tf32(As[cur][rb][ac]);
                af[mi][1] = f2tf32(As[cur][rb + 8][ac]);
                af[mi][2] = f2tf32(As[cur][rb][ac + 4]);
                af[mi][3] = f2tf32(As[cur][rb + 8][ac + 4]);
            }
            const int bk = ks * 8 + tig;
            unsigned bf[4][2];
            #pragma unroll
            for (int ni = 0; ni < 4; ni++) {
                const int nn = wn0 + ni * 8 + gid;
                bf[ni][0] = f2tf32(Bs[cur][bk][nn]);
                bf[ni][1] = f2tf32(Bs[cur][bk + 4][nn]);
            }
            #pragma unroll
            for (int mi = 0; mi < 4; mi++)
                #pragma unroll
                for (int ni = 0; ni < 4; ni++)
                    mma_tf32(c[mi][ni], af[mi], bf[ni]);
        }
        if (more) {
            const int nb = cur ^ 1;
            *(float4*)&As[nb][arow0][aq * 4] = pa0;
            *(float4*)&As[nb][arow0 + 64][aq * 4] = pa1;
            *(float4*)&Bs[nb][brow0][bq * 4] = pb0;
            *(float4*)&Bs[nb][brow0 + 8][bq * 4] = pb1;
            __syncthreads();
        }
    }

    // epilogue: add bias, store
    #pragma unroll
    for (int ni = 0; ni < 4; ni++) {
        const int cc = n0 + wn0 + ni * 8 + tig * 2;
        const float2 b2 = *(const float2*)&bias[cc];
        #pragma unroll
        for (int mi = 0; mi < 4; mi++) {
            const int r = m0 + wm0 + mi * 16 + gid;
            float2 v0 = make_float2(c[mi][ni][0] + b2.x, c[mi][ni][1] + b2.y);
            float2 v1 = make_float2(c[mi][ni][2] + b2.x, c[mi][ni][3] + b2.y);
            *(float2*)&Cmat[(size_t)r * N + cc] = v0;
            *(float2*)&Cmat[(size_t)(r + 8) * N + cc] = v1;
        }
    }
}

// ---------------- double-buffered 128x128x16 fp32x2 GEMM (experts) ----------------
__global__ __launch_bounds__(256, 2) void gemm128(
    const float* __restrict__ A, const float* __restrict__ Bt,
    const float* __restrict__ bias, float* __restrict__ Cmat,
    int M, int N, int K, int lda, int amode, int relu,
    long long sA, long long sB, long long sBias, long long sC)
{
    const int bz = blockIdx.z;
    A    += (size_t)sA * bz;
    Bt   += (size_t)sB * bz;
    bias += (size_t)sBias * bz;
    Cmat += (size_t)sC * bz;
    const int n0 = blockIdx.x * 128;
    const int m0 = blockIdx.y * 128;

    __shared__ float As[2][16][132];
    __shared__ float Bs[2][16][128];

    const int tid = threadIdx.x;
    const int tx = tid & 15, ty = tid >> 4;
    const int arow0 = tid >> 2, aq = tid & 3;
    const int brow0 = tid >> 5, bq = tid & 31;

    size_t ab0, ab1;
    { int m = m0 + arow0;
      ab0 = (amode == 0) ? (size_t)m * lda
                         : ((size_t)(m & (Bn - 1)) * Tn + (m >> 10)) * (size_t)lda; }
    { int m = m0 + arow0 + 64;
      ab1 = (amode == 0) ? (size_t)m * lda
                         : ((size_t)(m & (Bn - 1)) * Tn + (m >> 10)) * (size_t)lda; }
    const float* Ap0 = A + ab0 + aq * 4;
    const float* Ap1 = A + ab1 + aq * 4;
    const float* Bp0 = Bt + (size_t)brow0 * N + n0 + bq * 4;
    const float* Bp1 = Bt + (size_t)(brow0 + 8) * N + n0 + bq * 4;

    unsigned long long acc[8][4];
    #pragma unroll
    for (int i = 0; i < 8; i++)
        #pragma unroll
        for (int j = 0; j < 4; j++) acc[i][j] = 0ull;

    float4 pa0 = *(const float4*)(Ap0);
    float4 pa1 = *(const float4*)(Ap1);
    float4 pb0 = *(const float4*)(Bp0);
    float4 pb1 = *(const float4*)(Bp1);
    As[0][aq * 4 + 0][arow0] = pa0.x; As[0][aq * 4 + 1][arow0] = pa0.y;
    As[0][aq * 4 + 2][arow0] = pa0.z; As[0][aq * 4 + 3][arow0] = pa0.w;
    As[0][aq * 4 + 0][arow0 + 64] = pa1.x; As[0][aq * 4 + 1][arow0 + 64] = pa1.y;
    As[0][aq * 4 + 2][arow0 + 64] = pa1.z; As[0][aq * 4 + 3][arow0 + 64] = pa1.w;
    *(float4*)&Bs[0][brow0][bq * 4] = pb0;
    *(float4*)&Bs[0][brow0 + 8][bq * 4] = pb1;
    __syncthreads();

    const int nit = K >> 4;
    for (int it = 0; it < nit; ++it) {
        const int cur = it & 1;
        const bool more = (it + 1) < nit;
        if (more) {
            const int k0 = (it + 1) << 4;
            pa0 = *(const float4*)(Ap0 + k0);
            pa1 = *(const float4*)(Ap1 + k0);
            pb0 = *(const float4*)(Bp0 + (size_t)k0 * N);
            pb1 = *(const float4*)(Bp1 + (size_t)k0 * N);
        }
        #pragma unroll
        for (int k = 0; k < 16; k++) {
            float4 aA = *(const float4*)&As[cur][k][ty * 4];
            float4 aB = *(const float4*)&As[cur][k][64 + ty * 4];
            ulonglong2 bA = *(const ulonglong2*)&Bs[cur][k][tx * 4];
            ulonglong2 bB = *(const ulonglong2*)&Bs[cur][k][64 + tx * 4];
            unsigned long long b2[4] = { bA.x, bA.y, bB.x, bB.y };
            float a_[8] = { aA.x, aA.y, aA.z, aA.w, aB.x, aB.y, aB.z, aB.w };
            #pragma unroll
            for (int i = 0; i < 8; i++) {
                unsigned long long a2 = pack2(a_[i], a_[i]);
                #pragma unroll
                for (int j = 0; j < 4; j++) ffma2(acc[i][j], a2, b2[j]);
            }
        }
        if (more) {
            const int nb = cur ^ 1;
            As[nb][aq * 4 + 0][arow0] = pa0.x; As[nb][aq * 4 + 1][arow0] = pa0.y;
            As[nb][aq * 4 + 2][arow0] = pa0.z; As[nb][aq * 4 + 3][arow0] = pa0.w;
            As[nb][aq * 4 + 0][arow0 + 64] = pa1.x; As[nb][aq * 4 + 1][arow0 + 64] = pa1.y;
            As[nb][aq * 4 + 2][arow0 + 64] = pa1.z; As[nb][aq * 4 + 3][arow0 + 64] = pa1.w;
            *(float4*)&Bs[nb][brow0][bq * 4] = pb0;
            *(float4*)&Bs[nb][brow0 + 8][bq * 4] = pb1;
            __syncthreads();
        }
    }

    #pragma unroll
    for (int i = 0; i < 8; i++) {
        int r = (i < 4) ? (ty * 4 + i) : (64 + ty * 4 + (i - 4));
        size_t crow = (size_t)(m0 + r) * N;
        #pragma unroll
        for (int j = 0; j < 4; j++) {
            int c = n0 + ((j < 2) ? (tx * 4 + j * 2) : (64 + tx * 4 + (j - 2) * 2));
            float2 v = unpack2(acc[i][j]);
            v.x += bias[c]; v.y += bias[c + 1];
            if (relu) { v.x = fmaxf(v.x, 0.f); v.y = fmaxf(v.y, 0.f); }
            *(float2*)&Cmat[crow + c] = v;
        }
    }
}

// ---------------- persistent GRU layer with per-group (8-CTA) barriers ----------------
__global__ __launch_bounds__(256, 1) void gru_layer(
    const float* __restrict__ gi,    // [T,B,3H] with b_ih + b_hh(r,z) folded
    const float* __restrict__ wpack, // [8][256][96]
    const float* __restrict__ bhh,   // original b_hh (n-gate slice used)
    float* __restrict__ hseq,
    float* __restrict__ pb0, float* __restrict__ pb1,
    int mode)
{
    extern __shared__ float sm[];
    float* Wsm = sm;                       // [256][96]
    float* HsB = sm + 256 * 96;            // [2][16][68]

    const int bid = blockIdx.x;
    const int nblk = bid & 7;
    const int b0 = (bid >> 3) << 6;
    const int n0 = nblk << 5;
    const int tid = threadIdx.x;
    const int tx = tid & 15, ty = tid >> 4;
    const int hr = tid >> 2, hq = tid & 3;
    unsigned* cnt = g_grp_cnt + (bid >> 3) * 32;

    {
        const float4* ws = (const float4*)(wpack + (size_t)nblk * 256 * 96);
        float4* wd = (float4*)Wsm;
        #pragma unroll 4
        for (int i = tid; i < 256 * 96 / 4; i += 256) wd[i] = ws[i];
    }
    __syncthreads();

    const int nn0 = n0 + tx * 2;
    const float2 bn2 = *(const float2*)&bhh[2 * Hn + nn0];

    for (int t = 0; t < Tn; t++) {
        const float* hprev; float* hout;
        if (mode == 0) {
            hprev = hseq + (size_t)(t - 1) * (Bn * Hn);
            hout  = hseq + (size_t)t * (Bn * Hn);
        } else {
            hprev = (t & 1) ? pb1 : pb0;
            hout  = (t & 1) ? pb0 : pb1;
        }

        float2 gr[4], gz[4], gn[4], hp2[4];
        #pragma unroll
        for (int i = 0; i < 4; i++) {
            int b = b0 + ty * 4 + i;
            const float* gp = gi + ((size_t)t * Bn + b) * (3 * Hn);
            gr[i] = *(const float2*)(gp + nn0);
            gz[i] = *(const float2*)(gp + Hn + nn0);
            gn[i] = *(const float2*)(gp + 2 * Hn + nn0);
            hp2[i] = make_float2(0.f, 0.f);
            if (t > 0) hp2[i] = *(const float2*)(hprev + (size_t)b * Hn + nn0);
        }

        if (t > 0) {
            __syncthreads();
            if (tid == 0) {
                while (ld_acq_gpu(cnt) < (unsigned)(8 * t)) {}
            }
            __syncthreads();
        }

        unsigned long long accr[4], accz[4], accn[4];
        #pragma unroll
        for (int i = 0; i < 4; i++) { accr[i] = 0ull; accz[i] = 0ull; accn[i] = 0ull; }

        if (t > 0) {
            const float* Hp = hprev + (size_t)(b0 + hr) * Hn + (hq << 2);
            float4 ph = __ldcg((const float4*)Hp);

            float* H0 = HsB;
            H0[(hq * 4 + 0) * 68 + hr] = ph.x; H0[(hq * 4 + 1) * 68 + hr] = ph.y;
            H0[(hq * 4 + 2) * 68 + hr] = ph.z; H0[(hq * 4 + 3) * 68 + hr] = ph.w;
            __syncthreads();

            for (int it = 0; it < 16; ++it) {
                const int cur = it & 1;
                const bool more = it < 15;
                if (more) ph = __ldcg((const float4*)(Hp + ((it + 1) << 4)));

                const float* Hc = HsB + cur * (16 * 68);
                const float* Wb = Wsm + (it << 4) * 96;
                #pragma unroll
                for (int k = 0; k < 16; k++) {
                    float4 a4 = *(const float4*)(Hc + k * 68 + ty * 4);
                    const float* wk = Wb + k * 96;
                    unsigned long long br = *(const unsigned long long*)(wk + tx * 2);
                    unsigned long long bz = *(const unsigned long long*)(wk + 32 + tx * 2);
                    unsigned long long bn = *(const unsigned long long*)(wk + 64 + tx * 2);
                    float a_[4] = { a4.x, a4.y, a4.z, a4.w };
                    #pragma unroll
                    for (int i = 0; i < 4; i++) {
                        unsigned long long a2 = pack2(a_[i], a_[i]);
                        ffma2(accr[i], a2, br);
                        ffma2(accz[i], a2, bz);
                        ffma2(accn[i], a2, bn);
                    }
                }
                if (more) {
                    float* Hx = HsB + (cur ^ 1) * (16 * 68);
                    Hx[(hq * 4 + 0) * 68 + hr] = ph.x; Hx[(hq * 4 + 1) * 68 + hr] = ph.y;
                    Hx[(hq * 4 + 2) * 68 + hr] = ph.z; Hx[(hq * 4 + 3) * 68 + hr] = ph.w;
                    __syncthreads();
                }
            }
        }

        #pragma unroll
        for (int i = 0; i < 4; i++) {
            int b = b0 + ty * 4 + i;
            float2 r2 = unpack2(accr[i]), z2 = unpack2(accz[i]), n2 = unpack2(accn[i]);
            float rr[2] = { r2.x, r2.y }, zz[2] = { z2.x, z2.y }, nv[2] = { n2.x, n2.y };
            float grv[2] = { gr[i].x, gr[i].y }, gzv[2] = { gz[i].x, gz[i].y }, gnv[2] = { gn[i].x, gn[i].y };
            float bnn[2] = { bn2.x, bn2.y }, hpv[2] = { hp2[i].x, hp2[i].y };
            float outv[2];
            #pragma unroll
            for (int jj = 0; jj < 2; jj++) {
                float r = __fdividef(1.f, 1.f + __expf(-(grv[jj] + rr[jj])));
                float z = __fdividef(1.f, 1.f + __expf(-(gzv[jj] + zz[jj])));
                float a = gnv[jj] + r * (nv[jj] + bnn[jj]);
                float e = __expf(2.f * a);
                float nn = 1.f - __fdividef(2.f, e + 1.f);
                outv[jj] = (1.f - z) * nn + z * hpv[jj];
            }
            *(float2*)&hout[(size_t)b * Hn + nn0] = make_float2(outv[0], outv[1]);
        }

        __syncthreads();
        if (tid == 0) {
            __threadfence();
            atomicAdd(cnt, 1u);
        }
    }

    if (tid == 0 && nblk == 0) {
        while (ld_acq_gpu(cnt) < (unsigned)(8 * Tn)) {}
        atomicExch(cnt, 0u);
    }
}

// ---------------- soft cluster assignment q (Student-t, alpha=1) ----------------
__global__ __launch_bounds__(256) void qkernel(
    const float* __restrict__ z, const float* __restrict__ centers, float* __restrict__ q)
{
    __shared__ float cs[Kn * Hn];
    for (int i = threadIdx.x; i < Kn * Hn; i += 256) cs[i] = centers[i];
    __syncthreads();
    int warp = threadIdx.x >> 5, lane = threadIdx.x & 31;
    int b = blockIdx.x * 8 + warp;
    const float* zr = z + (size_t)b * Hn;
    float zv[8];
    #pragma unroll
    for (int i = 0; i < 8; i++) zv[i] = zr[lane + i * 32];
    float qk[Kn]; float s = 0.f;
    #pragma unroll
    for (int k = 0; k < Kn; k++) {
        float d2 = 0.f;
        #pragma unroll
        for (int i = 0; i < 8; i++) {
            float d = zv[i] - cs[k * Hn + lane + i * 32];
            d2 = fmaf(d, d, d2);
        }
        #pragma unroll
        for (int o = 16; o; o >>= 1) d2 += __shfl_xor_sync(0xffffffffu, d2, o);
        qk[k] = 1.f / (1.f + d2);
        s += qk[k];
    }
    if (lane == 0) {
        float inv = 1.f / s;
        #pragma unroll
        for (int k = 0; k < Kn; k++) q[b * Kn + k] = qk[k] * inv;
    }
}

// ---------------- final: logits + q-weighted combine ----------------
__global__ __launch_bounds__(256) void expert_out(
    const float* __restrict__ h2,  // [K,B,E2]
    const float* __restrict__ W3,  // [K,C,E2]
    const float* __restrict__ b3,  // [K,C]
    const float* __restrict__ q,   // [B,K]
    float* __restrict__ out)       // [B,C]
{
    int warp = threadIdx.x >> 5, lane = threadIdx.x & 31;
    int b = blockIdx.x * 8 + warp;
    float p0 = 0.f, p1 = 0.f;
    #pragma unroll
    for (int k = 0; k < Kn; k++) {
        const float* hr = h2 + ((size_t)k * Bn + b) * E2n;
        const float* w0 = W3 + (size_t)(k * 2 + 0) * E2n;
        const float* w1 = W3 + (size_t)(k * 2 + 1) * E2n;
        float d0 = 0.f, d1 = 0.f;
        #pragma unroll
        for (int i = 0; i < 8; i++) {
            float hv = hr[lane + i * 32];
            d0 = fmaf(hv, w0[lane + i * 32], d0);
            d1 = fmaf(hv, w1[lane + i * 32], d1);
        }
        #pragma unroll
        for (int o = 16; o; o >>= 1) {
            d0 += __shfl_xor_sync(0xffffffffu, d0, o);
            d1 += __shfl_xor_sync(0xffffffffu, d1, o);
        }
        float qv = q[b * Kn + k];
        p0 += qv * (d0 + b3[k * 2 + 0]);
        p1 += qv * (d1 + b3[k * 2 + 1]);
    }
    if (lane == 0) { out[b * 2 + 0] = p0; out[b * 2 + 1] = p1; }
}

// ---------------- launch ----------------
extern "C" void kernel_launch(void* const* d_in, const int* in_sizes, int n_in,
                              void* d_out, int out_size)
{
    const float* x      = (const float*)d_in[0];
    const float* W_ih0  = (const float*)d_in[1];
    const float* W_hh0  = (const float*)d_in[2];
    const float* b_ih0  = (const float*)d_in[3];
    const float* b_hh0  = (const float*)d_in[4];
    const float* W_ih1  = (const float*)d_in[5];
    const float* W_hh1  = (const float*)d_in[6];
    const float* b_ih1  = (const float*)d_in[7];
    const float* b_hh1  = (const float*)d_in[8];
    const float* cc     = (const float*)d_in[9];
    const float* eW1    = (const float*)d_in[10];
    const float* eb1    = (const float*)d_in[11];
    const float* eW2    = (const float*)d_in[12];
    const float* eb2    = (const float*)d_in[13];
    const float* eW3    = (const float*)d_in[14];
    const float* eb3    = (const float*)d_in[15];
    float* out = (float*)d_out;

    float *gi, *hseq, *hb0, *hb1, *q, *wih0, *wih1, *wp0, *wp1, *bs0, *bs1, *we1, *we2, *h1, *h2;
    cudaGetSymbolAddress((void**)&gi,   g_gi);
    cudaGetSymbolAddress((void**)&hseq, g_hseq);
    cudaGetSymbolAddress((void**)&hb0,  g_hbuf0);
    cudaGetSymbolAddress((void**)&hb1,  g_hbuf1);
    cudaGetSymbolAddress((void**)&q,    g_q);
    cudaGetSymbolAddress((void**)&wih0, g_Wt_ih0);
    cudaGetSymbolAddress((void**)&wih1, g_Wt_ih1);
    cudaGetSymbolAddress((void**)&wp0,  g_wp0);
    cudaGetSymbolAddress((void**)&wp1,  g_wp1);
    cudaGetSymbolAddress((void**)&bs0,  g_bsum0);
    cudaGetSymbolAddress((void**)&bs1,  g_bsum1);
    cudaGetSymbolAddress((void**)&we1,  g_Wt_e1);
    cudaGetSymbolAddress((void**)&we2,  g_Wt_e2);
    cudaGetSymbolAddress((void**)&h1,   g_h1);
    cudaGetSymbolAddress((void**)&h2,   g_h2);

    static int smem_set = 0;
    const int SMEM_GRU = (256 * 96 + 2 * 16 * 68) * 4;  // 107008 B
    if (!smem_set) {
        cudaFuncSetAttribute(gru_layer, cudaFuncAttributeMaxDynamicSharedMemorySize, SMEM_GRU);
        smem_set = 1;
    }

    // ---- launch 1: all transposes fused ----
    TJobs js;
    js.j[0] = { W_ih0, wih0, 3 * Hn, In,  In  / 32, (3 * Hn / 32) * (In  / 32), 0 };
    js.j[1] = { W_ih1, wih1, 3 * Hn, Hn,  Hn  / 32, (3 * Hn / 32) * (Hn  / 32), 0 };
    js.j[2] = { eW1,   we1,  E1n,    Hn,  Hn  / 32, (E1n / 32) * (Hn  / 32), 0 };
    js.j[3] = { eW2,   we2,  E2n,    E1n, E1n / 32, (E2n / 32) * (E1n / 32), 0 };
    js.j[1].off = js.j[0].off + js.j[0].tpb;
    js.j[2].off = js.j[1].off + js.j[1].tpb;
    js.j[3].off = js.j[2].off + js.j[2].tpb * Kn;
    int totalTiles = js.j[3].off + js.j[3].tpb * Kn;
    transpose_all<<<totalTiles, dim3(32, 8)>>>(js);

    // ---- launch 2: pack W_hh for both layers ----
    pack_whh<<<dim3(8, 8, 2), 256>>>(W_hh0, W_hh1, wp0, wp1);

    // ---- launch 3: fold b_hh(r,z) into gi bias ----
    bias_combine<<<1, 3 * Hn>>>(b_ih0, b_hh0, b_ih1, b_hh1, bs0, bs1);

    const int M0 = Tn * Bn;  // 131072

    // ---- gi0 = x @ W_ih0^T + bsum0 (tf32 tensor cores), stored [T,B,3H] ----
    gemm_tf32<<<dim3(3 * Hn / 128, M0 / 128), 256>>>(
        x, wih0, bs0, gi, M0, 3 * Hn, In, In, /*amode=*/1);

    // ---- layer-0 recurrence: ONE persistent launch ----
    gru_layer<<<NCTA, 256, SMEM_GRU>>>(gi, wp0, b_hh0, hseq, nullptr, nullptr, 0);

    // ---- gi1 = h_l0 @ W_ih1^T + bsum1 (tf32 tensor cores) ----
    gemm_tf32<<<dim3(3 * Hn / 128, M0 / 128), 256>>>(
        hseq, wih1, bs1, gi, M0, 3 * Hn, Hn, Hn, /*amode=*/0);

    // ---- layer-1 recurrence: ONE persistent launch (final h in hb0) ----
    gru_layer<<<NCTA, 256, SMEM_GRU>>>(gi, wp1, b_hh1, nullptr, hb0, hb1, 1);

    // ---- q [B,K] ----
    qkernel<<<Bn / 8, 256>>>(hb0, cc, q);

    // ---- experts (fp32, batched over K in grid.z) ----
    gemm128<<<dim3(E1n / 128, Bn / 128, Kn), 256>>>(
        hb0, we1, eb1, h1, Bn, E1n, Hn, Hn, 0, /*relu=*/1,
        0, (long long)Hn * E1n, E1n, (long long)Bn * E1n);
    gemm128<<<dim3(E2n / 128, Bn / 128, Kn), 256>>>(
        h1, we2, eb2, h2, Bn, E2n, E1n, E1n, 0, /*relu=*/1,
        (long long)Bn * E1n, (long long)E1n * E2n, E2n, (long long)Bn * E2n);

    // ---- logits + q-weighted combine -> out [B,C] ----
    expert_out<<<Bn / 8, 256>>>(h2, eW3, eb3, q, out);
}